// round 1
// baseline (speedup 1.0000x reference)
#include <cuda_runtime.h>
#include <cuda_bf16.h>
#include <math.h>

// Problem constants (shapes are fixed by the dataset)
#define NDRUGS 8192
#define KDIM   256
#define LOG2F_ 0.69314718055994531f

// ---- scratch (no allocations allowed -> __device__ globals) ----
__device__ __align__(128) float g_genc[NDRUGS * KDIM];   // global encoder output
__device__ __align__(128) float g_lenc[NDRUGS * KDIM];   // local  encoder output

#define BT   64                 // score GEMM tile
#define NBLK ((NDRUGS/BT)*(NDRUGS/BT))   // 128*128 = 16384
__device__ float g_partials[2 * NBLK];   // [0:NBLK) pos, [NBLK:2N) neg

// ============================================================================
// FF encoder: out = relu(relu(relu(x@w1+b1)@w2+b2)@w3+b3) + x@ws + bs
// One block handles 16 rows; thread t owns output column t; weights stream
// through L2 (all 512 blocks read the same 256KB matrices).
// ============================================================================
__device__ __forceinline__ void ff_layer(const float in[16][KDIM],
                                         const float* __restrict__ w,
                                         const float* __restrict__ b,
                                         float out[16][KDIM], int c)
{
    float acc[16];
#pragma unroll
    for (int r = 0; r < 16; r++) acc[r] = 0.f;
#pragma unroll 4
    for (int k = 0; k < KDIM; k++) {
        float wv = __ldg(w + k * KDIM + c);
#pragma unroll
        for (int r = 0; r < 16; r++) acc[r] = fmaf(in[r][k], wv, acc[r]);
    }
    float bv = __ldg(b + c);
#pragma unroll
    for (int r = 0; r < 16; r++) out[r][c] = fmaxf(acc[r] + bv, 0.f);
}

__global__ void __launch_bounds__(256)
ff_kernel(const float* __restrict__ x,
          const float* __restrict__ w1, const float* __restrict__ b1,
          const float* __restrict__ w2, const float* __restrict__ b2,
          const float* __restrict__ w3, const float* __restrict__ b3,
          const float* __restrict__ ws, const float* __restrict__ bs,
          int which)   // 0 -> g_genc, 1 -> g_lenc
{
    __shared__ float xs[16][KDIM];
    __shared__ float ha[16][KDIM];
    __shared__ float hb[16][KDIM];

    const int tid  = threadIdx.x;
    const int row0 = blockIdx.x * 16;

    // load 16x256 input tile (vectorized)
    {
        const float4* xp  = (const float4*)(x + (size_t)row0 * KDIM);
        float4*       xsp = (float4*)&xs[0][0];
#pragma unroll
        for (int i = tid; i < 16 * KDIM / 4; i += 256) xsp[i] = xp[i];
    }
    __syncthreads();

    ff_layer(xs, w1, b1, ha, tid);  __syncthreads();
    ff_layer(ha, w2, b2, hb, tid);  __syncthreads();
    ff_layer(hb, w3, b3, ha, tid);  __syncthreads();   // h3 now in ha

    // shortcut: out = ha + xs@ws + bs
    {
        float acc[16];
#pragma unroll
        for (int r = 0; r < 16; r++) acc[r] = 0.f;
#pragma unroll 4
        for (int k = 0; k < KDIM; k++) {
            float wv = __ldg(ws + k * KDIM + tid);
#pragma unroll
            for (int r = 0; r < 16; r++) acc[r] = fmaf(xs[r][k], wv, acc[r]);
        }
        float bv = __ldg(bs + tid);
        float* dst = which ? g_lenc : g_genc;
#pragma unroll
        for (int r = 0; r < 16; r++)
            dst[(size_t)(row0 + r) * KDIM + tid] = ha[r][tid] + acc[r] + bv;
    }
}

// ============================================================================
// Score GEMM + fused JSD epilogue.
// res[i][j] = dot(l_enc[i], g_enc[j]);  a = adj[i][j]
//   a==1: pos += LOG2 - softplus(-res)        (neg term is exactly 0)
//   a==0: neg += softplus(-res) + res - LOG2  (pos term is exactly 0)
// 64x64 block tile, 256 threads, 4x4 micro-tile, K-chunks of 16.
// ============================================================================
__global__ void __launch_bounds__(256)
score_kernel(const float* __restrict__ adj)
{
    constexpr int KC  = 16;
    constexpr int LDT = BT + 4;      // smem pad: stride 68 words, keeps f4 align
    __shared__ float ls[KC][LDT];
    __shared__ float gs[KC][LDT];
    __shared__ float red[512];

    const int tid = threadIdx.x;
    const int bx  = blockIdx.x, by = blockIdx.y;
    const int i0  = by * BT, j0 = bx * BT;
    const int tx  = tid & 15, ty = tid >> 4;

    const int lr = tid >> 2;            // 0..63  tile row for loads
    const int lk = (tid & 3) * 4;       // 0,4,8,12 k offset for loads

    float acc[4][4];
#pragma unroll
    for (int a = 0; a < 4; a++)
#pragma unroll
        for (int b = 0; b < 4; b++) acc[a][b] = 0.f;

    const float* Lp = g_lenc + (size_t)(i0 + lr) * KDIM + lk;
    const float* Gp = g_genc + (size_t)(j0 + lr) * KDIM + lk;

    for (int kc = 0; kc < KDIM; kc += KC) {
        float4 va = *(const float4*)(Lp + kc);
        float4 vb = *(const float4*)(Gp + kc);
        ls[lk + 0][lr] = va.x; ls[lk + 1][lr] = va.y;
        ls[lk + 2][lr] = va.z; ls[lk + 3][lr] = va.w;
        gs[lk + 0][lr] = vb.x; gs[lk + 1][lr] = vb.y;
        gs[lk + 2][lr] = vb.z; gs[lk + 3][lr] = vb.w;
        __syncthreads();

#pragma unroll
        for (int k = 0; k < KC; k++) {
            float4 av = *(const float4*)&ls[k][ty * 4];
            float4 bv = *(const float4*)&gs[k][tx * 4];
            float  A[4] = {av.x, av.y, av.z, av.w};
            float  B[4] = {bv.x, bv.y, bv.z, bv.w};
#pragma unroll
            for (int ri = 0; ri < 4; ri++)
#pragma unroll
                for (int rj = 0; rj < 4; rj++)
                    acc[ri][rj] = fmaf(A[ri], B[rj], acc[ri][rj]);
        }
        __syncthreads();
    }

    // fused epilogue: softplus(-r) = max(-r,0) + log1p(exp(-|r|))
    float pos = 0.f, neg = 0.f;
#pragma unroll
    for (int ri = 0; ri < 4; ri++) {
        const int i = i0 + ty * 4 + ri;
        float4 av = *(const float4*)(adj + (size_t)i * NDRUGS + j0 + tx * 4);
        float aa[4] = {av.x, av.y, av.z, av.w};
#pragma unroll
        for (int rj = 0; rj < 4; rj++) {
            float r = acc[ri][rj];
            float s = fmaxf(-r, 0.f) + log1pf(__expf(-fabsf(r)));
            if (aa[rj] > 0.5f) pos += LOG2F_ - s;
            else               neg += s + r - LOG2F_;
        }
    }

    // deterministic block reduction -> per-block partial (no float atomics)
    red[tid] = pos; red[256 + tid] = neg;
    __syncthreads();
#pragma unroll
    for (int s = 128; s > 0; s >>= 1) {
        if (tid < s) { red[tid] += red[tid + s]; red[256 + tid] += red[256 + tid + s]; }
        __syncthreads();
    }
    if (tid == 0) {
        int bid = by * gridDim.x + bx;
        g_partials[bid]        = red[0];
        g_partials[NBLK + bid] = red[256];
    }
}

// ============================================================================
// Final reduction -> scalar, fixed-order double accumulation (deterministic)
// ============================================================================
__global__ void __launch_bounds__(1024)
reduce_kernel(float* __restrict__ out)
{
    __shared__ double sp[1024];
    __shared__ double sn[1024];
    const int tid = threadIdx.x;
    double p = 0.0, n = 0.0;
    for (int i = tid; i < NBLK; i += 1024) {
        p += (double)g_partials[i];
        n += (double)g_partials[NBLK + i];
    }
    sp[tid] = p; sn[tid] = n;
    __syncthreads();
    for (int s = 512; s > 0; s >>= 1) {
        if (tid < s) { sp[tid] += sp[tid + s]; sn[tid] += sn[tid + s]; }
        __syncthreads();
    }
    if (tid == 0) {
        double E_pos = sp[0] / (double)NDRUGS;
        double E_neg = sn[0] / ((double)NDRUGS * (double)(NDRUGS - 1));
        out[0] = (float)(E_neg - E_pos);
    }
}

// ============================================================================
// launch
// ============================================================================
extern "C" void kernel_launch(void* const* d_in, const int* in_sizes, int n_in,
                              void* d_out, int out_size)
{
    const float* emb  = (const float*)d_in[0];
    const float* feat = (const float*)d_in[1];
    const float* adj  = (const float*)d_in[2];
    // d_in[3] = num_drugs (int scalar), compile-time known = 8192
    const float* g_w1 = (const float*)d_in[4];
    const float* g_b1 = (const float*)d_in[5];
    const float* g_w2 = (const float*)d_in[6];
    const float* g_b2 = (const float*)d_in[7];
    const float* g_w3 = (const float*)d_in[8];
    const float* g_b3 = (const float*)d_in[9];
    const float* g_ws = (const float*)d_in[10];
    const float* g_bs = (const float*)d_in[11];
    const float* l_w1 = (const float*)d_in[12];
    const float* l_b1 = (const float*)d_in[13];
    const float* l_w2 = (const float*)d_in[14];
    const float* l_b2 = (const float*)d_in[15];
    const float* l_w3 = (const float*)d_in[16];
    const float* l_b3 = (const float*)d_in[17];
    const float* l_ws = (const float*)d_in[18];
    const float* l_bs = (const float*)d_in[19];
    float* out = (float*)d_out;

    ff_kernel<<<NDRUGS / 16, 256>>>(emb,  g_w1, g_b1, g_w2, g_b2, g_w3, g_b3,
                                    g_ws, g_bs, 0);
    ff_kernel<<<NDRUGS / 16, 256>>>(feat, l_w1, l_b1, l_w2, l_b2, l_w3, l_b3,
                                    l_ws, l_bs, 1);

    dim3 grid(NDRUGS / BT, NDRUGS / BT);
    score_kernel<<<grid, 256>>>(adj);

    reduce_kernel<<<1, 1024>>>(out);
}

// round 3
// speedup vs baseline: 1.9365x; 1.9365x over previous
#include <cuda_runtime.h>
#include <cuda_bf16.h>
#include <math.h>
#include <stdint.h>

// Problem constants (fixed by the dataset)
#define NDRUGS 8192
#define KDIM   256
#define LOG2F_ 0.69314718055994531f

// ============================ device scratch ================================
__device__ __align__(1024) __nv_bfloat16 g_genc_bf[NDRUGS * KDIM];
__device__ __align__(1024) __nv_bfloat16 g_lenc_bf[NDRUGS * KDIM];

#define BT   128
#define NBLK ((NDRUGS / BT) * (NDRUGS / BT))   // 64*64 = 4096
__device__ float g_partials[2 * NBLK];

// =========================== small PTX helpers ==============================
__device__ __forceinline__ uint32_t smem_u32(const void* p) {
    uint32_t a;
    asm("{ .reg .u64 t; cvta.to.shared.u64 t, %1; cvt.u32.u64 %0, t; }"
        : "=r"(a) : "l"(p));
    return a;
}
__device__ __forceinline__ void cp_async16(uint32_t dst, const void* src) {
    asm volatile("cp.async.cg.shared.global [%0], [%1], 16;"
                 :: "r"(dst), "l"(src) : "memory");
}
__device__ __forceinline__ void cp_async_commit() {
    asm volatile("cp.async.commit_group;" ::: "memory");
}
__device__ __forceinline__ void cp_async_wait_all() {
    asm volatile("cp.async.wait_group 0;" ::: "memory");
}
__device__ __forceinline__ void mma_bf16(float& d0, float& d1, float& d2, float& d3,
                                         uint32_t a0, uint32_t a1, uint32_t a2,
                                         uint32_t a3, uint32_t b0, uint32_t b1) {
    asm volatile(
        "mma.sync.aligned.m16n8k16.row.col.f32.bf16.bf16.f32 "
        "{%0,%1,%2,%3}, {%4,%5,%6,%7}, {%8,%9}, {%0,%1,%2,%3};"
        : "+f"(d0), "+f"(d1), "+f"(d2), "+f"(d3)
        : "r"(a0), "r"(a1), "r"(a2), "r"(a3), "r"(b0), "r"(b1));
}

// ============================================================================
// FF encoder (fp32 SIMT math, emits bf16 encodings)
// ============================================================================
__device__ __forceinline__ void ff_layer(const float in[16][KDIM],
                                         const float* __restrict__ w,
                                         const float* __restrict__ b,
                                         float out[16][KDIM], int c)
{
    float acc[16];
#pragma unroll
    for (int r = 0; r < 16; r++) acc[r] = 0.f;
#pragma unroll 4
    for (int k = 0; k < KDIM; k++) {
        float wv = __ldg(w + k * KDIM + c);
#pragma unroll
        for (int r = 0; r < 16; r++) acc[r] = fmaf(in[r][k], wv, acc[r]);
    }
    float bv = __ldg(b + c);
#pragma unroll
    for (int r = 0; r < 16; r++) out[r][c] = fmaxf(acc[r] + bv, 0.f);
}

__global__ void __launch_bounds__(256)
ff_kernel(const float* __restrict__ x,
          const float* __restrict__ w1, const float* __restrict__ b1,
          const float* __restrict__ w2, const float* __restrict__ b2,
          const float* __restrict__ w3, const float* __restrict__ b3,
          const float* __restrict__ ws, const float* __restrict__ bs,
          int which)   // 0 -> g_genc_bf, 1 -> g_lenc_bf
{
    __shared__ float xs[16][KDIM];
    __shared__ float ha[16][KDIM];
    __shared__ float hb[16][KDIM];

    const int tid  = threadIdx.x;
    const int row0 = blockIdx.x * 16;

    {
        const float4* xp  = (const float4*)(x + (size_t)row0 * KDIM);
        float4*       xsp = (float4*)&xs[0][0];
#pragma unroll
        for (int i = tid; i < 16 * KDIM / 4; i += 256) xsp[i] = xp[i];
    }
    __syncthreads();

    ff_layer(xs, w1, b1, ha, tid);  __syncthreads();
    ff_layer(ha, w2, b2, hb, tid);  __syncthreads();
    ff_layer(hb, w3, b3, ha, tid);  __syncthreads();

    {
        float acc[16];
#pragma unroll
        for (int r = 0; r < 16; r++) acc[r] = 0.f;
#pragma unroll 4
        for (int k = 0; k < KDIM; k++) {
            float wv = __ldg(ws + k * KDIM + tid);
#pragma unroll
            for (int r = 0; r < 16; r++) acc[r] = fmaf(xs[r][k], wv, acc[r]);
        }
        float bv = __ldg(bs + tid);
        __nv_bfloat16* dst = which ? g_lenc_bf : g_genc_bf;
#pragma unroll
        for (int r = 0; r < 16; r++)
            dst[(size_t)(row0 + r) * KDIM + tid] =
                __float2bfloat16(ha[r][tid] + acc[r] + bv);
    }
}

// ============================================================================
// Score GEMM (mma.sync bf16, 128x128 CTA tile, 8 warps of 32x64) + JSD epilogue
// SMEM (dynamic):
//   As : 128 x 264 bf16   (67584 B)  row stride 264 -> conflict-free frags
//   Bs : 128 x 264 bf16   (67584 B)
//   Adj: 128 x 132 float  (67584 B)
//   red: 512 float
// ============================================================================
#define LDAB  264
#define LDADJ 132
#define SM_A   0
#define SM_B   67584
#define SM_ADJ 135168
#define SM_RED 202752
#define SM_SIZE (202752 + 2048)

__global__ void __launch_bounds__(256)
score_kernel(const float* __restrict__ adj)
{
    extern __shared__ char smem[];
    __nv_bfloat16* As  = (__nv_bfloat16*)(smem + SM_A);
    __nv_bfloat16* Bs  = (__nv_bfloat16*)(smem + SM_B);
    float*         Adj = (float*)(smem + SM_ADJ);
    float*         red = (float*)(smem + SM_RED);

    const int tid  = threadIdx.x;
    const int lane = tid & 31;
    const int warp = tid >> 5;
    const int gid  = lane >> 2;    // 0..7
    const int tig  = lane & 3;     // 0..3
    const int wm   = warp >> 1;    // 0..3 -> 32-row slab
    const int wn   = warp & 1;     // 0..1 -> 64-col slab
    const int mrow = wm * 32;
    const int ncol = wn * 64;

    const int i0 = blockIdx.y * BT;
    const int j0 = blockIdx.x * BT;

    // ---- stage adj tile via cp.async (overlaps with A/B load + MMA) ----
    {
        const uint32_t adj_s = smem_u32(Adj);
#pragma unroll
        for (int it = 0; it < 16; it++) {
            int c   = tid + it * 256;          // 16B chunk, 0..4095
            int row = c >> 5;
            int cw  = (c & 31) * 4;            // float col
            cp_async16(adj_s + (uint32_t)(row * LDADJ + cw) * 4,
                       adj + (size_t)(i0 + row) * NDRUGS + j0 + cw);
        }
        cp_async_commit();
    }

    // ---- load A (l_enc rows i0..) / B (g_enc rows j0..) into padded smem ----
    {
        const uint4* Ap = (const uint4*)(g_lenc_bf + (size_t)i0 * KDIM);
        const uint4* Bp = (const uint4*)(g_genc_bf + (size_t)j0 * KDIM);
#pragma unroll
        for (int it = 0; it < 16; it++) {
            int c   = tid + it * 256;          // 16B chunk, 0..4095
            int row = c >> 5;
            int kc  = (c & 31) * 8;            // bf16 col
            uint4 va = Ap[c];
            uint4 vb = Bp[c];
            *(uint4*)(As + row * LDAB + kc) = va;
            *(uint4*)(Bs + row * LDAB + kc) = vb;
        }
    }
    __syncthreads();

    // ---- MMA mainloop: K=256 in 16 steps of k=16 ----
    float acc[2][8][4];
#pragma unroll
    for (int mt = 0; mt < 2; mt++)
#pragma unroll
        for (int nt = 0; nt < 8; nt++)
#pragma unroll
            for (int q = 0; q < 4; q++) acc[mt][nt][q] = 0.f;

    const __nv_bfloat16* a_lo = As + (mrow + gid) * LDAB + tig * 2;
    const __nv_bfloat16* a_hi = a_lo + 8 * LDAB;
    const __nv_bfloat16* b_p  = Bs + (ncol + gid) * LDAB + tig * 2;

#pragma unroll 4
    for (int ks = 0; ks < 16; ks++) {
        const int k0 = ks * 16;
        uint32_t bfr[8][2];
#pragma unroll
        for (int nt = 0; nt < 8; nt++) {
            bfr[nt][0] = *(const uint32_t*)(b_p + nt * 8 * LDAB + k0);
            bfr[nt][1] = *(const uint32_t*)(b_p + nt * 8 * LDAB + k0 + 8);
        }
#pragma unroll
        for (int mt = 0; mt < 2; mt++) {
            uint32_t a0 = *(const uint32_t*)(a_lo + mt * 16 * LDAB + k0);
            uint32_t a1 = *(const uint32_t*)(a_hi + mt * 16 * LDAB + k0);
            uint32_t a2 = *(const uint32_t*)(a_lo + mt * 16 * LDAB + k0 + 8);
            uint32_t a3 = *(const uint32_t*)(a_hi + mt * 16 * LDAB + k0 + 8);
#pragma unroll
            for (int nt = 0; nt < 8; nt++)
                mma_bf16(acc[mt][nt][0], acc[mt][nt][1],
                         acc[mt][nt][2], acc[mt][nt][3],
                         a0, a1, a2, a3, bfr[nt][0], bfr[nt][1]);
        }
    }

    cp_async_wait_all();
    __syncthreads();

    // ---- fused JSD epilogue ----
    float pos = 0.f, neg = 0.f;
#pragma unroll
    for (int mt = 0; mt < 2; mt++) {
        const int r0 = mrow + mt * 16 + gid;          // tile-local row
#pragma unroll
        for (int nt = 0; nt < 8; nt++) {
            const int c0 = ncol + nt * 8 + tig * 2;
            float2 alo = *(const float2*)(Adj + r0 * LDADJ + c0);
            float2 ahi = *(const float2*)(Adj + (r0 + 8) * LDADJ + c0);
            float aa[4] = {alo.x, alo.y, ahi.x, ahi.y};
#pragma unroll
            for (int q = 0; q < 4; q++) {
                float r = acc[mt][nt][q];
                float s = fmaxf(-r, 0.f) + log1pf(__expf(-fabsf(r)));
                if (aa[q] > 0.5f) pos += LOG2F_ - s;
                else              neg += s + r - LOG2F_;
            }
        }
    }

    // ---- deterministic block reduction ----
    red[tid] = pos; red[256 + tid] = neg;
    __syncthreads();
#pragma unroll
    for (int s = 128; s > 0; s >>= 1) {
        if (tid < s) { red[tid] += red[tid + s]; red[256 + tid] += red[256 + tid + s]; }
        __syncthreads();
    }
    if (tid == 0) {
        int bid = blockIdx.y * gridDim.x + blockIdx.x;
        g_partials[bid]        = red[0];
        g_partials[NBLK + bid] = red[256];
    }
}

// ============================================================================
// Final reduction (deterministic double accumulation)
// ============================================================================
__global__ void __launch_bounds__(1024)
reduce_kernel(float* __restrict__ out)
{
    __shared__ double sp[1024];
    __shared__ double sn[1024];
    const int tid = threadIdx.x;
    double p = 0.0, n = 0.0;
#pragma unroll
    for (int i = tid; i < NBLK; i += 1024) {
        p += (double)g_partials[i];
        n += (double)g_partials[NBLK + i];
    }
    sp[tid] = p; sn[tid] = n;
    __syncthreads();
    for (int s = 512; s > 0; s >>= 1) {
        if (tid < s) { sp[tid] += sp[tid + s]; sn[tid] += sn[tid + s]; }
        __syncthreads();
    }
    if (tid == 0) {
        double E_pos = sp[0] / (double)NDRUGS;
        double E_neg = sn[0] / ((double)NDRUGS * (double)(NDRUGS - 1));
        out[0] = (float)(E_neg - E_pos);
    }
}

// ============================================================================
// launch
// ============================================================================
extern "C" void kernel_launch(void* const* d_in, const int* in_sizes, int n_in,
                              void* d_out, int out_size)
{
    const float* emb  = (const float*)d_in[0];
    const float* feat = (const float*)d_in[1];
    const float* adj  = (const float*)d_in[2];
    const float* g_w1 = (const float*)d_in[4];
    const float* g_b1 = (const float*)d_in[5];
    const float* g_w2 = (const float*)d_in[6];
    const float* g_b2 = (const float*)d_in[7];
    const float* g_w3 = (const float*)d_in[8];
    const float* g_b3 = (const float*)d_in[9];
    const float* g_ws = (const float*)d_in[10];
    const float* g_bs = (const float*)d_in[11];
    const float* l_w1 = (const float*)d_in[12];
    const float* l_b1 = (const float*)d_in[13];
    const float* l_w2 = (const float*)d_in[14];
    const float* l_b2 = (const float*)d_in[15];
    const float* l_w3 = (const float*)d_in[16];
    const float* l_b3 = (const float*)d_in[17];
    const float* l_ws = (const float*)d_in[18];
    const float* l_bs = (const float*)d_in[19];
    float* out = (float*)d_out;

    cudaFuncSetAttribute(score_kernel,
                         cudaFuncAttributeMaxDynamicSharedMemorySize, SM_SIZE);

    ff_kernel<<<NDRUGS / 16, 256>>>(emb,  g_w1, g_b1, g_w2, g_b2, g_w3, g_b3,
                                    g_ws, g_bs, 0);
    ff_kernel<<<NDRUGS / 16, 256>>>(feat, l_w1, l_b1, l_w2, l_b2, l_w3, l_b3,
                                    l_ws, l_bs, 1);

    dim3 grid(NDRUGS / BT, NDRUGS / BT);
    score_kernel<<<grid, 256, SM_SIZE>>>(adj);

    reduce_kernel<<<1, 1024>>>(out);
}

// round 4
// speedup vs baseline: 2.0897x; 1.0791x over previous
#include <cuda_runtime.h>
#include <cuda_bf16.h>
#include <math.h>
#include <stdint.h>

// Problem constants (fixed by the dataset)
#define NDRUGS 8192
#define KDIM   256
#define LOG2F_ 0.69314718055994531f

// ============================ device scratch ================================
__device__ __align__(1024) __nv_bfloat16 g_genc_bf[NDRUGS * KDIM];
__device__ __align__(1024) __nv_bfloat16 g_lenc_bf[NDRUGS * KDIM];

#define BT   128
#define NBLK ((NDRUGS / BT) * (NDRUGS / BT))   // 64*64 = 4096
__device__ float g_partials[2 * NBLK];

// =========================== small PTX helpers ==============================
__device__ __forceinline__ uint32_t smem_u32(const void* p) {
    uint32_t a;
    asm("{ .reg .u64 t; cvta.to.shared.u64 t, %1; cvt.u32.u64 %0, t; }"
        : "=r"(a) : "l"(p));
    return a;
}
__device__ __forceinline__ void cp_async16(uint32_t dst, const void* src) {
    asm volatile("cp.async.cg.shared.global [%0], [%1], 16;"
                 :: "r"(dst), "l"(src) : "memory");
}
__device__ __forceinline__ void cp_async_commit() {
    asm volatile("cp.async.commit_group;" ::: "memory");
}
__device__ __forceinline__ void cp_async_wait_all() {
    asm volatile("cp.async.wait_group 0;" ::: "memory");
}
__device__ __forceinline__ void mma_bf16(float& d0, float& d1, float& d2, float& d3,
                                         uint32_t a0, uint32_t a1, uint32_t a2,
                                         uint32_t a3, uint32_t b0, uint32_t b1) {
    asm volatile(
        "mma.sync.aligned.m16n8k16.row.col.f32.bf16.bf16.f32 "
        "{%0,%1,%2,%3}, {%4,%5,%6,%7}, {%8,%9}, {%0,%1,%2,%3};"
        : "+f"(d0), "+f"(d1), "+f"(d2), "+f"(d3)
        : "r"(a0), "r"(a1), "r"(a2), "r"(a3), "r"(b0), "r"(b1));
}

// ============================================================================
// FF encoder (fp32 SIMT math, emits bf16 encodings)
// ============================================================================
__device__ __forceinline__ void ff_layer(const float in[16][KDIM],
                                         const float* __restrict__ w,
                                         const float* __restrict__ b,
                                         float out[16][KDIM], int c)
{
    float acc[16];
#pragma unroll
    for (int r = 0; r < 16; r++) acc[r] = 0.f;
#pragma unroll 4
    for (int k = 0; k < KDIM; k++) {
        float wv = __ldg(w + k * KDIM + c);
#pragma unroll
        for (int r = 0; r < 16; r++) acc[r] = fmaf(in[r][k], wv, acc[r]);
    }
    float bv = __ldg(b + c);
#pragma unroll
    for (int r = 0; r < 16; r++) out[r][c] = fmaxf(acc[r] + bv, 0.f);
}

__global__ void __launch_bounds__(256)
ff_kernel(const float* __restrict__ x,
          const float* __restrict__ w1, const float* __restrict__ b1,
          const float* __restrict__ w2, const float* __restrict__ b2,
          const float* __restrict__ w3, const float* __restrict__ b3,
          const float* __restrict__ ws, const float* __restrict__ bs,
          int which)   // 0 -> g_genc_bf, 1 -> g_lenc_bf
{
    __shared__ float xs[16][KDIM];
    __shared__ float ha[16][KDIM];
    __shared__ float hb[16][KDIM];

    const int tid  = threadIdx.x;
    const int row0 = blockIdx.x * 16;

    {
        const float4* xp  = (const float4*)(x + (size_t)row0 * KDIM);
        float4*       xsp = (float4*)&xs[0][0];
#pragma unroll
        for (int i = tid; i < 16 * KDIM / 4; i += 256) xsp[i] = xp[i];
    }
    __syncthreads();

    ff_layer(xs, w1, b1, ha, tid);  __syncthreads();
    ff_layer(ha, w2, b2, hb, tid);  __syncthreads();
    ff_layer(hb, w3, b3, ha, tid);  __syncthreads();

    {
        float acc[16];
#pragma unroll
        for (int r = 0; r < 16; r++) acc[r] = 0.f;
#pragma unroll 4
        for (int k = 0; k < KDIM; k++) {
            float wv = __ldg(ws + k * KDIM + tid);
#pragma unroll
            for (int r = 0; r < 16; r++) acc[r] = fmaf(xs[r][k], wv, acc[r]);
        }
        float bv = __ldg(bs + tid);
        __nv_bfloat16* dst = which ? g_lenc_bf : g_genc_bf;
#pragma unroll
        for (int r = 0; r < 16; r++)
            dst[(size_t)(row0 + r) * KDIM + tid] =
                __float2bfloat16(ha[r][tid] + acc[r] + bv);
    }
}

// ============================================================================
// Score GEMM (mma.sync bf16, 128x128 CTA tile, 8 warps of 32x64) + JSD epilogue
// ============================================================================
#define LDAB  264
#define LDADJ 132
#define SM_A   0
#define SM_B   67584
#define SM_ADJ 135168
#define SM_RED 202752
#define SM_SIZE (202752 + 2048)

__global__ void __launch_bounds__(256)
score_kernel(const float* __restrict__ adj)
{
    extern __shared__ char smem[];
    __nv_bfloat16* As  = (__nv_bfloat16*)(smem + SM_A);
    __nv_bfloat16* Bs  = (__nv_bfloat16*)(smem + SM_B);
    float*         Adj = (float*)(smem + SM_ADJ);
    float*         red = (float*)(smem + SM_RED);

    const int tid  = threadIdx.x;
    const int lane = tid & 31;
    const int warp = tid >> 5;
    const int gid  = lane >> 2;    // 0..7
    const int tig  = lane & 3;     // 0..3
    const int wm   = warp >> 1;    // 0..3 -> 32-row slab
    const int wn   = warp & 1;     // 0..1 -> 64-col slab
    const int mrow = wm * 32;
    const int ncol = wn * 64;

    const int i0 = blockIdx.y * BT;
    const int j0 = blockIdx.x * BT;

    // ---- stage adj tile via cp.async (overlaps with A/B load + MMA) ----
    {
        const uint32_t adj_s = smem_u32(Adj);
#pragma unroll
        for (int it = 0; it < 16; it++) {
            int c   = tid + it * 256;          // 16B chunk, 0..4095
            int row = c >> 5;
            int cw  = (c & 31) * 4;            // float col
            cp_async16(adj_s + (uint32_t)(row * LDADJ + cw) * 4,
                       adj + (size_t)(i0 + row) * NDRUGS + j0 + cw);
        }
        cp_async_commit();
    }

    // ---- load A (l_enc rows i0..) / B (g_enc rows j0..) into padded smem ----
    {
        const uint4* Ap = (const uint4*)(g_lenc_bf + (size_t)i0 * KDIM);
        const uint4* Bp = (const uint4*)(g_genc_bf + (size_t)j0 * KDIM);
#pragma unroll
        for (int it = 0; it < 16; it++) {
            int c   = tid + it * 256;          // 16B chunk, 0..4095
            int row = c >> 5;
            int kc  = (c & 31) * 8;            // bf16 col
            uint4 va = Ap[c];
            uint4 vb = Bp[c];
            *(uint4*)(As + row * LDAB + kc) = va;
            *(uint4*)(Bs + row * LDAB + kc) = vb;
        }
    }
    __syncthreads();

    // ---- MMA mainloop: K=256 in 16 steps of k=16 ----
    float acc[2][8][4];
#pragma unroll
    for (int mt = 0; mt < 2; mt++)
#pragma unroll
        for (int nt = 0; nt < 8; nt++)
#pragma unroll
            for (int q = 0; q < 4; q++) acc[mt][nt][q] = 0.f;

    const __nv_bfloat16* a_lo = As + (mrow + gid) * LDAB + tig * 2;
    const __nv_bfloat16* a_hi = a_lo + 8 * LDAB;
    const __nv_bfloat16* b_p  = Bs + (ncol + gid) * LDAB + tig * 2;

#pragma unroll 4
    for (int ks = 0; ks < 16; ks++) {
        const int k0 = ks * 16;
        uint32_t bfr[8][2];
#pragma unroll
        for (int nt = 0; nt < 8; nt++) {
            bfr[nt][0] = *(const uint32_t*)(b_p + nt * 8 * LDAB + k0);
            bfr[nt][1] = *(const uint32_t*)(b_p + nt * 8 * LDAB + k0 + 8);
        }
#pragma unroll
        for (int mt = 0; mt < 2; mt++) {
            uint32_t a0 = *(const uint32_t*)(a_lo + mt * 16 * LDAB + k0);
            uint32_t a1 = *(const uint32_t*)(a_hi + mt * 16 * LDAB + k0);
            uint32_t a2 = *(const uint32_t*)(a_lo + mt * 16 * LDAB + k0 + 8);
            uint32_t a3 = *(const uint32_t*)(a_hi + mt * 16 * LDAB + k0 + 8);
#pragma unroll
            for (int nt = 0; nt < 8; nt++)
                mma_bf16(acc[mt][nt][0], acc[mt][nt][1],
                         acc[mt][nt][2], acc[mt][nt][3],
                         a0, a1, a2, a3, bfr[nt][0], bfr[nt][1]);
        }
    }

    cp_async_wait_all();
    __syncthreads();

    // ---- fused JSD epilogue (fast-math softplus: 2 MUFU + few ALU) ----
    float pos = 0.f, neg = 0.f;
#pragma unroll
    for (int mt = 0; mt < 2; mt++) {
        const int r0 = mrow + mt * 16 + gid;          // tile-local row
#pragma unroll
        for (int nt = 0; nt < 8; nt++) {
            const int c0 = ncol + nt * 8 + tig * 2;
            float2 alo = *(const float2*)(Adj + r0 * LDADJ + c0);
            float2 ahi = *(const float2*)(Adj + (r0 + 8) * LDADJ + c0);
            float aa[4] = {alo.x, alo.y, ahi.x, ahi.y};
#pragma unroll
            for (int q = 0; q < 4; q++) {
                float r = acc[mt][nt][q];
                // softplus(-r) = max(-r,0) + log(1 + exp(-|r|))
                float s = fmaxf(-r, 0.f) + __logf(1.f + __expf(-fabsf(r)));
                if (aa[q] > 0.5f) pos += LOG2F_ - s;
                else              neg += s + r - LOG2F_;
            }
        }
    }

    // ---- deterministic block reduction ----
    red[tid] = pos; red[256 + tid] = neg;
    __syncthreads();
#pragma unroll
    for (int s = 128; s > 0; s >>= 1) {
        if (tid < s) { red[tid] += red[tid + s]; red[256 + tid] += red[256 + tid + s]; }
        __syncthreads();
    }
    if (tid == 0) {
        int bid = blockIdx.y * gridDim.x + blockIdx.x;
        g_partials[bid]        = red[0];
        g_partials[NBLK + bid] = red[256];
    }
}

// ============================================================================
// Final reduction (deterministic double accumulation, vectorized loads)
// ============================================================================
__global__ void __launch_bounds__(512)
reduce_kernel(float* __restrict__ out)
{
    __shared__ double sp[512];
    __shared__ double sn[512];
    const int tid = threadIdx.x;
    double p = 0.0, n = 0.0;
#pragma unroll
    for (int i = tid; i < NBLK / 4; i += 512) {
        float4 vp = *(const float4*)(g_partials + i * 4);
        float4 vn = *(const float4*)(g_partials + NBLK + i * 4);
        p += (double)vp.x + (double)vp.y + (double)vp.z + (double)vp.w;
        n += (double)vn.x + (double)vn.y + (double)vn.z + (double)vn.w;
    }
    sp[tid] = p; sn[tid] = n;
    __syncthreads();
#pragma unroll
    for (int s = 256; s > 0; s >>= 1) {
        if (tid < s) { sp[tid] += sp[tid + s]; sn[tid] += sn[tid + s]; }
        __syncthreads();
    }
    if (tid == 0) {
        double E_pos = sp[0] / (double)NDRUGS;
        double E_neg = sn[0] / ((double)NDRUGS * (double)(NDRUGS - 1));
        out[0] = (float)(E_neg - E_pos);
    }
}

// ============================================================================
// launch
// ============================================================================
extern "C" void kernel_launch(void* const* d_in, const int* in_sizes, int n_in,
                              void* d_out, int out_size)
{
    const float* emb  = (const float*)d_in[0];
    const float* feat = (const float*)d_in[1];
    const float* adj  = (const float*)d_in[2];
    const float* g_w1 = (const float*)d_in[4];
    const float* g_b1 = (const float*)d_in[5];
    const float* g_w2 = (const float*)d_in[6];
    const float* g_b2 = (const float*)d_in[7];
    const float* g_w3 = (const float*)d_in[8];
    const float* g_b3 = (const float*)d_in[9];
    const float* g_ws = (const float*)d_in[10];
    const float* g_bs = (const float*)d_in[11];
    const float* l_w1 = (const float*)d_in[12];
    const float* l_b1 = (const float*)d_in[13];
    const float* l_w2 = (const float*)d_in[14];
    const float* l_b2 = (const float*)d_in[15];
    const float* l_w3 = (const float*)d_in[16];
    const float* l_b3 = (const float*)d_in[17];
    const float* l_ws = (const float*)d_in[18];
    const float* l_bs = (const float*)d_in[19];
    float* out = (float*)d_out;

    cudaFuncSetAttribute(score_kernel,
                         cudaFuncAttributeMaxDynamicSharedMemorySize, SM_SIZE);

    ff_kernel<<<NDRUGS / 16, 256>>>(emb,  g_w1, g_b1, g_w2, g_b2, g_w3, g_b3,
                                    g_ws, g_bs, 0);
    ff_kernel<<<NDRUGS / 16, 256>>>(feat, l_w1, l_b1, l_w2, l_b2, l_w3, l_b3,
                                    l_ws, l_bs, 1);

    dim3 grid(NDRUGS / BT, NDRUGS / BT);
    score_kernel<<<grid, 256, SM_SIZE>>>(adj);

    reduce_kernel<<<1, 512>>>(out);
}

// round 6
// speedup vs baseline: 2.5590x; 1.2246x over previous
#include <cuda_runtime.h>
#include <cuda_bf16.h>
#include <math.h>
#include <stdint.h>

// Problem constants (fixed by the dataset)
#define NDRUGS 8192
#define KDIM   256
#define LOG2F_ 0.69314718055994531f

// ============================ device scratch ================================
__device__ __align__(1024) __nv_bfloat16 g_genc_bf[NDRUGS * KDIM];
__device__ __align__(1024) __nv_bfloat16 g_lenc_bf[NDRUGS * KDIM];

#define BT   128
#define NBLK ((NDRUGS / BT) * (NDRUGS / BT))   // 64*64 = 4096
__device__ float g_partials[2 * NBLK];

// =========================== small PTX helpers ==============================
__device__ __forceinline__ uint32_t smem_u32(const void* p) {
    uint32_t a;
    asm("{ .reg .u64 t; cvta.to.shared.u64 t, %1; cvt.u32.u64 %0, t; }"
        : "=r"(a) : "l"(p));
    return a;
}
__device__ __forceinline__ void cp_async16(uint32_t dst, const void* src) {
    asm volatile("cp.async.cg.shared.global [%0], [%1], 16;"
                 :: "r"(dst), "l"(src) : "memory");
}
__device__ __forceinline__ void cp_async_commit() {
    asm volatile("cp.async.commit_group;" ::: "memory");
}
__device__ __forceinline__ void cp_async_wait_all() {
    asm volatile("cp.async.wait_group 0;" ::: "memory");
}
__device__ __forceinline__ void mma_bf16(float& d0, float& d1, float& d2, float& d3,
                                         uint32_t a0, uint32_t a1, uint32_t a2,
                                         uint32_t a3, uint32_t b0, uint32_t b1) {
    asm volatile(
        "mma.sync.aligned.m16n8k16.row.col.f32.bf16.bf16.f32 "
        "{%0,%1,%2,%3}, {%4,%5,%6,%7}, {%8,%9}, {%0,%1,%2,%3};"
        : "+f"(d0), "+f"(d1), "+f"(d2), "+f"(d3)
        : "r"(a0), "r"(a1), "r"(a2), "r"(a3), "r"(b0), "r"(b1));
}

// ============================================================================
// FF encoder (fp32 SIMT math, float4 smem reads, emits bf16 encodings)
// ============================================================================
__device__ __forceinline__ void ff_layer(const float in[16][KDIM],
                                         const float* __restrict__ w,
                                         const float* __restrict__ b,
                                         float out[16][KDIM], int c)
{
    float acc[16];
#pragma unroll
    for (int r = 0; r < 16; r++) acc[r] = 0.f;
#pragma unroll 2
    for (int k = 0; k < KDIM; k += 4) {
        float w0 = __ldg(w + (k + 0) * KDIM + c);
        float w1 = __ldg(w + (k + 1) * KDIM + c);
        float w2 = __ldg(w + (k + 2) * KDIM + c);
        float w3 = __ldg(w + (k + 3) * KDIM + c);
#pragma unroll
        for (int r = 0; r < 16; r++) {
            float4 iv = *(const float4*)&in[r][k];
            acc[r] = fmaf(iv.x, w0, acc[r]);
            acc[r] = fmaf(iv.y, w1, acc[r]);
            acc[r] = fmaf(iv.z, w2, acc[r]);
            acc[r] = fmaf(iv.w, w3, acc[r]);
        }
    }
    float bv = __ldg(b + c);
#pragma unroll
    for (int r = 0; r < 16; r++) out[r][c] = fmaxf(acc[r] + bv, 0.f);
}

__global__ void __launch_bounds__(256)
ff_kernel(const float* __restrict__ x,
          const float* __restrict__ w1, const float* __restrict__ b1,
          const float* __restrict__ w2, const float* __restrict__ b2,
          const float* __restrict__ w3, const float* __restrict__ b3,
          const float* __restrict__ ws, const float* __restrict__ bs,
          int which)   // 0 -> g_genc_bf, 1 -> g_lenc_bf
{
    __shared__ float xs[16][KDIM];
    __shared__ float ha[16][KDIM];
    __shared__ float hb[16][KDIM];

    const int tid  = threadIdx.x;
    const int row0 = blockIdx.x * 16;

    {
        const float4* xp  = (const float4*)(x + (size_t)row0 * KDIM);
        float4*       xsp = (float4*)&xs[0][0];
#pragma unroll
        for (int i = tid; i < 16 * KDIM / 4; i += 256) xsp[i] = xp[i];
    }
    __syncthreads();

    ff_layer(xs, w1, b1, ha, tid);  __syncthreads();
    ff_layer(ha, w2, b2, hb, tid);  __syncthreads();
    ff_layer(hb, w3, b3, ha, tid);  __syncthreads();

    {
        float acc[16];
#pragma unroll
        for (int r = 0; r < 16; r++) acc[r] = 0.f;
#pragma unroll 2
        for (int k = 0; k < KDIM; k += 4) {
            float w0 = __ldg(ws + (k + 0) * KDIM + tid);
            float w1v = __ldg(ws + (k + 1) * KDIM + tid);
            float w2v = __ldg(ws + (k + 2) * KDIM + tid);
            float w3v = __ldg(ws + (k + 3) * KDIM + tid);
#pragma unroll
            for (int r = 0; r < 16; r++) {
                float4 iv = *(const float4*)&xs[r][k];
                acc[r] = fmaf(iv.x, w0,  acc[r]);
                acc[r] = fmaf(iv.y, w1v, acc[r]);
                acc[r] = fmaf(iv.z, w2v, acc[r]);
                acc[r] = fmaf(iv.w, w3v, acc[r]);
            }
        }
        float bv = __ldg(bs + tid);
        __nv_bfloat16* dst = which ? g_lenc_bf : g_genc_bf;
#pragma unroll
        for (int r = 0; r < 16; r++)
            dst[(size_t)(row0 + r) * KDIM + tid] =
                __float2bfloat16(ha[r][tid] + acc[r] + bv);
    }
}

// ============================================================================
// Score GEMM (mma.sync bf16, 128x128 CTA tile, K chunked 2x128) + JSD epilogue
// SMEM: As 128x136 bf16 (34816 B) + Bs same = 69632 B  -> 3 CTAs/SM
// adj is read directly from global in the epilogue (no smem staging).
// ============================================================================
#define LDK    136          // bf16 row stride for one 128-wide K chunk
#define SM_A   0
#define SM_B   34816
#define SM_SIZE 69632

__global__ void __launch_bounds__(256)
score_kernel(const float* __restrict__ adj)
{
    extern __shared__ char smem[];
    __nv_bfloat16* As = (__nv_bfloat16*)(smem + SM_A);
    __nv_bfloat16* Bs = (__nv_bfloat16*)(smem + SM_B);

    const int tid  = threadIdx.x;
    const int lane = tid & 31;
    const int warp = tid >> 5;
    const int gid  = lane >> 2;    // 0..7
    const int tig  = lane & 3;     // 0..3
    const int wm   = warp >> 1;    // 0..3 -> 32-row slab
    const int wn   = warp & 1;     // 0..1 -> 64-col slab
    const int mrow = wm * 32;
    const int ncol = wn * 64;

    const int i0 = blockIdx.y * BT;
    const int j0 = blockIdx.x * BT;

    float acc[2][8][4];
#pragma unroll
    for (int mt = 0; mt < 2; mt++)
#pragma unroll
        for (int nt = 0; nt < 8; nt++)
#pragma unroll
            for (int q = 0; q < 4; q++) acc[mt][nt][q] = 0.f;

    const uint32_t as_s = smem_u32(As);
    const uint32_t bs_s = smem_u32(Bs);
    const __nv_bfloat16* a_lo = As + (mrow + gid) * LDK + tig * 2;
    const __nv_bfloat16* a_hi = a_lo + 8 * LDK;
    const __nv_bfloat16* b_p  = Bs + (ncol + gid) * LDK + tig * 2;

#pragma unroll 1
    for (int kc = 0; kc < 2; kc++) {
        // ---- stage A/B K-chunk via cp.async ----
        // 2048 16B-chunks per array, 16 chunks per 128-bf16 row
#pragma unroll
        for (int it = 0; it < 8; it++) {
            int c   = tid + it * 256;    // 0..2047
            int row = c >> 4;            // 0..127
            int kq  = (c & 15) * 8;      // bf16 col within chunk, 0..120
            uint32_t soff = (uint32_t)(row * LDK + kq) * 2;
            cp_async16(as_s + soff,
                       g_lenc_bf + (size_t)(i0 + row) * KDIM + kc * 128 + kq);
            cp_async16(bs_s + soff,
                       g_genc_bf + (size_t)(j0 + row) * KDIM + kc * 128 + kq);
        }
        cp_async_commit();
        cp_async_wait_all();
        __syncthreads();

        // ---- 8 MMA steps over this K chunk ----
#pragma unroll
        for (int ks = 0; ks < 8; ks++) {
            const int k0 = ks * 16;
            uint32_t bfr[8][2];
#pragma unroll
            for (int nt = 0; nt < 8; nt++) {
                bfr[nt][0] = *(const uint32_t*)(b_p + nt * 8 * LDK + k0);
                bfr[nt][1] = *(const uint32_t*)(b_p + nt * 8 * LDK + k0 + 8);
            }
#pragma unroll
            for (int mt = 0; mt < 2; mt++) {
                uint32_t a0 = *(const uint32_t*)(a_lo + mt * 16 * LDK + k0);
                uint32_t a1 = *(const uint32_t*)(a_hi + mt * 16 * LDK + k0);
                uint32_t a2 = *(const uint32_t*)(a_lo + mt * 16 * LDK + k0 + 8);
                uint32_t a3 = *(const uint32_t*)(a_hi + mt * 16 * LDK + k0 + 8);
#pragma unroll
                for (int nt = 0; nt < 8; nt++)
                    mma_bf16(acc[mt][nt][0], acc[mt][nt][1],
                             acc[mt][nt][2], acc[mt][nt][3],
                             a0, a1, a2, a3, bfr[nt][0], bfr[nt][1]);
            }
        }
        __syncthreads();
    }

    // ---- fused JSD epilogue, adj read directly from global ----
    float pos = 0.f, neg = 0.f;
#pragma unroll
    for (int mt = 0; mt < 2; mt++) {
        const int r0 = i0 + mrow + mt * 16 + gid;     // global row
#pragma unroll
        for (int nt = 0; nt < 8; nt++) {
            const int c0 = j0 + ncol + nt * 8 + tig * 2;
            float2 alo = __ldg((const float2*)(adj + (size_t)r0 * NDRUGS + c0));
            float2 ahi = __ldg((const float2*)(adj + (size_t)(r0 + 8) * NDRUGS + c0));
            float aa[4] = {alo.x, alo.y, ahi.x, ahi.y};
#pragma unroll
            for (int q = 0; q < 4; q++) {
                float r = acc[mt][nt][q];
                // softplus(-r) = max(-r,0) + log(1 + exp(-|r|))
                float s = fmaxf(-r, 0.f) + __logf(1.f + __expf(-fabsf(r)));
                if (aa[q] > 0.5f) pos += LOG2F_ - s;
                else              neg += s + r - LOG2F_;
            }
        }
    }

    // ---- deterministic block reduction (reuse As smem) ----
    float* red = (float*)As;
    __syncthreads();
    red[tid] = pos; red[256 + tid] = neg;
    __syncthreads();
#pragma unroll
    for (int s = 128; s > 0; s >>= 1) {
        if (tid < s) { red[tid] += red[tid + s]; red[256 + tid] += red[256 + tid + s]; }
        __syncthreads();
    }
    if (tid == 0) {
        int bid = blockIdx.y * gridDim.x + blockIdx.x;
        g_partials[bid]        = red[0];
        g_partials[NBLK + bid] = red[256];
    }
}

// ============================================================================
// Final reduction (deterministic double accumulation, vectorized loads)
// ============================================================================
__global__ void __launch_bounds__(512)
reduce_kernel(float* __restrict__ out)
{
    __shared__ double sp[512];
    __shared__ double sn[512];
    const int tid = threadIdx.x;
    double p = 0.0, n = 0.0;
#pragma unroll
    for (int i = tid; i < NBLK / 4; i += 512) {
        float4 vp = *(const float4*)(g_partials + i * 4);
        float4 vn = *(const float4*)(g_partials + NBLK + i * 4);
        p += (double)vp.x + (double)vp.y + (double)vp.z + (double)vp.w;
        n += (double)vn.x + (double)vn.y + (double)vn.z + (double)vn.w;
    }
    sp[tid] = p; sn[tid] = n;
    __syncthreads();
#pragma unroll
    for (int s = 256; s > 0; s >>= 1) {
        if (tid < s) { sp[tid] += sp[tid + s]; sn[tid] += sn[tid + s]; }
        __syncthreads();
    }
    if (tid == 0) {
        double E_pos = sp[0] / (double)NDRUGS;
        double E_neg = sn[0] / ((double)NDRUGS * (double)(NDRUGS - 1));
        out[0] = (float)(E_neg - E_pos);
    }
}

// ============================================================================
// launch
// ============================================================================
extern "C" void kernel_launch(void* const* d_in, const int* in_sizes, int n_in,
                              void* d_out, int out_size)
{
    const float* emb  = (const float*)d_in[0];
    const float* feat = (const float*)d_in[1];
    const float* adj  = (const float*)d_in[2];
    const float* g_w1 = (const float*)d_in[4];
    const float* g_b1 = (const float*)d_in[5];
    const float* g_w2 = (const float*)d_in[6];
    const float* g_b2 = (const float*)d_in[7];
    const float* g_w3 = (const float*)d_in[8];
    const float* g_b3 = (const float*)d_in[9];
    const float* g_ws = (const float*)d_in[10];
    const float* g_bs = (const float*)d_in[11];
    const float* l_w1 = (const float*)d_in[12];
    const float* l_b1 = (const float*)d_in[13];
    const float* l_w2 = (const float*)d_in[14];
    const float* l_b2 = (const float*)d_in[15];
    const float* l_w3 = (const float*)d_in[16];
    const float* l_b3 = (const float*)d_in[17];
    const float* l_ws = (const float*)d_in[18];
    const float* l_bs = (const float*)d_in[19];
    float* out = (float*)d_out;

    cudaFuncSetAttribute(score_kernel,
                         cudaFuncAttributeMaxDynamicSharedMemorySize, SM_SIZE);

    ff_kernel<<<NDRUGS / 16, 256>>>(emb,  g_w1, g_b1, g_w2, g_b2, g_w3, g_b3,
                                    g_ws, g_bs, 0);
    ff_kernel<<<NDRUGS / 16, 256>>>(feat, l_w1, l_b1, l_w2, l_b2, l_w3, l_b3,
                                    l_ws, l_bs, 1);

    dim3 grid(NDRUGS / BT, NDRUGS / BT);
    score_kernel<<<grid, 256, SM_SIZE>>>(adj);

    reduce_kernel<<<1, 512>>>(out);
}

// round 7
// speedup vs baseline: 3.0761x; 1.2021x over previous
#include <cuda_runtime.h>
#include <cuda_bf16.h>
#include <math.h>
#include <stdint.h>

// Problem constants (fixed by the dataset)
#define NDRUGS 8192
#define KDIM   256
#define LOG2F_ 0.69314718055994531f

// ============================ device scratch ================================
__device__ __align__(1024) __nv_bfloat16 g_genc_bf[NDRUGS * KDIM];
__device__ __align__(1024) __nv_bfloat16 g_lenc_bf[NDRUGS * KDIM];

#define BT   128
#define NBLK ((NDRUGS / BT) * (NDRUGS / BT))   // 64*64 = 4096
__device__ float g_partials[2 * NBLK];

// =========================== small PTX helpers ==============================
__device__ __forceinline__ uint32_t smem_u32(const void* p) {
    uint32_t a;
    asm("{ .reg .u64 t; cvta.to.shared.u64 t, %1; cvt.u32.u64 %0, t; }"
        : "=r"(a) : "l"(p));
    return a;
}
__device__ __forceinline__ void cp_async16(uint32_t dst, const void* src) {
    asm volatile("cp.async.cg.shared.global [%0], [%1], 16;"
                 :: "r"(dst), "l"(src) : "memory");
}
__device__ __forceinline__ void cp_async_commit() {
    asm volatile("cp.async.commit_group;" ::: "memory");
}
template <int N>
__device__ __forceinline__ void cp_async_wait() {
    asm volatile("cp.async.wait_group %0;" :: "n"(N) : "memory");
}
__device__ __forceinline__ void prefetch_l2(const void* p) {
    asm volatile("prefetch.global.L2 [%0];" :: "l"(p));
}
__device__ __forceinline__ void ldmatrix_x4(uint32_t& r0, uint32_t& r1,
                                            uint32_t& r2, uint32_t& r3,
                                            uint32_t addr) {
    asm volatile("ldmatrix.sync.aligned.m8n8.x4.shared.b16 {%0,%1,%2,%3}, [%4];"
                 : "=r"(r0), "=r"(r1), "=r"(r2), "=r"(r3) : "r"(addr));
}
__device__ __forceinline__ void mma_bf16(float& d0, float& d1, float& d2, float& d3,
                                         uint32_t a0, uint32_t a1, uint32_t a2,
                                         uint32_t a3, uint32_t b0, uint32_t b1) {
    asm volatile(
        "mma.sync.aligned.m16n8k16.row.col.f32.bf16.bf16.f32 "
        "{%0,%1,%2,%3}, {%4,%5,%6,%7}, {%8,%9}, {%0,%1,%2,%3};"
        : "+f"(d0), "+f"(d1), "+f"(d2), "+f"(d3)
        : "r"(a0), "r"(a1), "r"(a2), "r"(a3), "r"(b0), "r"(b1));
}

// ============================================================================
// FF encoder (fp32 SIMT, both encoders in one launch via blockIdx.y)
// ============================================================================
__device__ __forceinline__ void ff_layer(const float in[16][KDIM],
                                         const float* __restrict__ w,
                                         const float* __restrict__ b,
                                         float out[16][KDIM], int c)
{
    float acc[16];
#pragma unroll
    for (int r = 0; r < 16; r++) acc[r] = 0.f;
#pragma unroll 2
    for (int k = 0; k < KDIM; k += 4) {
        float w0 = __ldg(w + (k + 0) * KDIM + c);
        float w1 = __ldg(w + (k + 1) * KDIM + c);
        float w2 = __ldg(w + (k + 2) * KDIM + c);
        float w3 = __ldg(w + (k + 3) * KDIM + c);
#pragma unroll
        for (int r = 0; r < 16; r++) {
            float4 iv = *(const float4*)&in[r][k];
            acc[r] = fmaf(iv.x, w0, acc[r]);
            acc[r] = fmaf(iv.y, w1, acc[r]);
            acc[r] = fmaf(iv.z, w2, acc[r]);
            acc[r] = fmaf(iv.w, w3, acc[r]);
        }
    }
    float bv = __ldg(b + c);
#pragma unroll
    for (int r = 0; r < 16; r++) out[r][c] = fmaxf(acc[r] + bv, 0.f);
}

__global__ void __launch_bounds__(256)
ff_kernel(const float* __restrict__ xg, const float* __restrict__ xl,
          const float* __restrict__ gw1, const float* __restrict__ gb1,
          const float* __restrict__ gw2, const float* __restrict__ gb2,
          const float* __restrict__ gw3, const float* __restrict__ gb3,
          const float* __restrict__ gws, const float* __restrict__ gbs,
          const float* __restrict__ lw1, const float* __restrict__ lb1,
          const float* __restrict__ lw2, const float* __restrict__ lb2,
          const float* __restrict__ lw3, const float* __restrict__ lb3,
          const float* __restrict__ lws, const float* __restrict__ lbs)
{
    __shared__ float xs[16][KDIM];
    __shared__ float ha[16][KDIM];
    __shared__ float hb[16][KDIM];

    const int which = blockIdx.y;
    const float* x  = which ? xl  : xg;
    const float* w1 = which ? lw1 : gw1;  const float* b1 = which ? lb1 : gb1;
    const float* w2 = which ? lw2 : gw2;  const float* b2 = which ? lb2 : gb2;
    const float* w3 = which ? lw3 : gw3;  const float* b3 = which ? lb3 : gb3;
    const float* ws = which ? lws : gws;  const float* bs = which ? lbs : gbs;

    const int tid  = threadIdx.x;
    const int row0 = blockIdx.x * 16;

    {
        const float4* xp  = (const float4*)(x + (size_t)row0 * KDIM);
        float4*       xsp = (float4*)&xs[0][0];
#pragma unroll
        for (int i = tid; i < 16 * KDIM / 4; i += 256) xsp[i] = xp[i];
    }
    __syncthreads();

    ff_layer(xs, w1, b1, ha, tid);  __syncthreads();
    ff_layer(ha, w2, b2, hb, tid);  __syncthreads();
    ff_layer(hb, w3, b3, ha, tid);  __syncthreads();

    {
        float acc[16];
#pragma unroll
        for (int r = 0; r < 16; r++) acc[r] = 0.f;
#pragma unroll 2
        for (int k = 0; k < KDIM; k += 4) {
            float w0  = __ldg(ws + (k + 0) * KDIM + tid);
            float w1v = __ldg(ws + (k + 1) * KDIM + tid);
            float w2v = __ldg(ws + (k + 2) * KDIM + tid);
            float w3v = __ldg(ws + (k + 3) * KDIM + tid);
#pragma unroll
            for (int r = 0; r < 16; r++) {
                float4 iv = *(const float4*)&xs[r][k];
                acc[r] = fmaf(iv.x, w0,  acc[r]);
                acc[r] = fmaf(iv.y, w1v, acc[r]);
                acc[r] = fmaf(iv.z, w2v, acc[r]);
                acc[r] = fmaf(iv.w, w3v, acc[r]);
            }
        }
        float bv = __ldg(bs + tid);
        __nv_bfloat16* dst = which ? g_lenc_bf : g_genc_bf;
#pragma unroll
        for (int r = 0; r < 16; r++)
            dst[(size_t)(row0 + r) * KDIM + tid] =
                __float2bfloat16(ha[r][tid] + acc[r] + bv);
    }
}

// ============================================================================
// Score GEMM: mma.sync bf16, 128x128 CTA tile, 4 K-chunks of 64, 2-stage
// cp.async pipeline, ldmatrix fragment loads, fused JSD epilogue.
// SMEM: 2 stages x (A 128x72 + B 128x72) bf16 = 73728 B
// ============================================================================
#define LDK     72                 // bf16 row stride for a 64-wide K chunk
#define STG_A   (128 * LDK * 2)    // 18432 B per array
#define STG_SZ  (2 * STG_A)        // 36864 B per stage (A+B)
#define SM_SIZE (2 * STG_SZ)       // 73728 B

__global__ void __launch_bounds__(256, 2)
score_kernel(const float* __restrict__ adj)
{
    extern __shared__ char smem[];
    const uint32_t s_base = smem_u32(smem);

    const int tid  = threadIdx.x;
    const int lane = tid & 31;
    const int warp = tid >> 5;
    const int gid  = lane >> 2;    // 0..7
    const int tig  = lane & 3;     // 0..3
    const int mrow = (warp >> 1) * 32;
    const int ncol = (warp & 1) * 64;

    const int i0 = blockIdx.y * BT;
    const int j0 = blockIdx.x * BT;

    // ---- L2 prefetch of the adj tile (overlaps whole mainloop) ----
#pragma unroll
    for (int t = tid; t < 512; t += 256) {
        int row = t >> 2, seg = t & 3;
        prefetch_l2(adj + (size_t)(i0 + row) * NDRUGS + j0 + seg * 32);
    }

    // ---- staging lambda data: 1024 16B-chunks per array per stage ----
    const int lrow = tid >> 3;           // c>>3 base for it-loop below
    const int lkq  = (tid & 7) * 8;

    // issue cp.async for K-chunk kc into stage st
    auto issue = [&](int kc, int st) {
        const uint32_t a_s = s_base + st * STG_SZ;
        const uint32_t b_s = a_s + STG_A;
#pragma unroll
        for (int it = 0; it < 4; it++) {
            int row = lrow + it * 32;                 // 0..127
            uint32_t soff = (uint32_t)(row * LDK + lkq) * 2;
            const size_t goff = (size_t)row * KDIM + kc * 64 + lkq;
            cp_async16(a_s + soff, g_lenc_bf + (size_t)i0 * KDIM + goff);
            cp_async16(b_s + soff, g_genc_bf + (size_t)j0 * KDIM + goff);
        }
        cp_async_commit();
    };

    // ---- ldmatrix per-lane base addresses ----
    // A frag: lanes 0-7 rows r0-7 k0; 8-15 rows r8-15 k0; 16-23 r0-7 k8; 24-31 r8-15 k8
    const int a_row  = mrow + (lane & 7) + ((lane >> 3) & 1) * 8;
    const int a_koff = (lane >> 4) * 8;
    const uint32_t a_lane = (uint32_t)(a_row * LDK + a_koff) * 2;
    // B frag (x4 covers nt, nt+1): lanes 0-15 n-rows of nt (k0/k8), 16-31 nt+1
    const int b_row  = ncol + (lane & 7) + (lane >> 4) * 8;
    const int b_koff = ((lane >> 3) & 1) * 8;
    const uint32_t b_lane = (uint32_t)(b_row * LDK + b_koff) * 2;

    float acc[2][8][4];
#pragma unroll
    for (int mt = 0; mt < 2; mt++)
#pragma unroll
        for (int nt = 0; nt < 8; nt++)
#pragma unroll
            for (int q = 0; q < 4; q++) acc[mt][nt][q] = 0.f;

    issue(0, 0);

#pragma unroll 1
    for (int kc = 0; kc < 4; kc++) {
        const int st = kc & 1;
        if (kc < 3) issue(kc + 1, st ^ 1);
        if (kc < 3) cp_async_wait<1>(); else cp_async_wait<0>();
        __syncthreads();

        const uint32_t a_s = s_base + st * STG_SZ + a_lane;
        const uint32_t b_s = s_base + st * STG_SZ + STG_A + b_lane;

#pragma unroll
        for (int ks = 0; ks < 4; ks++) {
            const uint32_t k0b = (uint32_t)(ks * 16) * 2;
            uint32_t bfr[8][2];
#pragma unroll
            for (int ntp = 0; ntp < 4; ntp++) {
                uint32_t r0, r1, r2, r3;
                ldmatrix_x4(r0, r1, r2, r3,
                            b_s + (uint32_t)(ntp * 16 * LDK) * 2 + k0b);
                bfr[2 * ntp][0]     = r0; bfr[2 * ntp][1]     = r1;
                bfr[2 * ntp + 1][0] = r2; bfr[2 * ntp + 1][1] = r3;
            }
#pragma unroll
            for (int mt = 0; mt < 2; mt++) {
                uint32_t a0, a1, a2, a3;
                ldmatrix_x4(a0, a1, a2, a3,
                            a_s + (uint32_t)(mt * 16 * LDK) * 2 + k0b);
#pragma unroll
                for (int nt = 0; nt < 8; nt++)
                    mma_bf16(acc[mt][nt][0], acc[mt][nt][1],
                             acc[mt][nt][2], acc[mt][nt][3],
                             a0, a1, a2, a3, bfr[nt][0], bfr[nt][1]);
            }
        }
        __syncthreads();
    }

    // ---- fused JSD epilogue, adj from L2 (prefetched) ----
    float pos = 0.f, neg = 0.f;
#pragma unroll
    for (int mt = 0; mt < 2; mt++) {
        const int r0 = i0 + mrow + mt * 16 + gid;     // global row
#pragma unroll
        for (int nt = 0; nt < 8; nt++) {
            const int c0 = j0 + ncol + nt * 8 + tig * 2;
            float2 alo = __ldg((const float2*)(adj + (size_t)r0 * NDRUGS + c0));
            float2 ahi = __ldg((const float2*)(adj + (size_t)(r0 + 8) * NDRUGS + c0));
            float aa[4] = {alo.x, alo.y, ahi.x, ahi.y};
#pragma unroll
            for (int q = 0; q < 4; q++) {
                float r = acc[mt][nt][q];
                float s = fmaxf(-r, 0.f) + __logf(1.f + __expf(-fabsf(r)));
                if (aa[q] > 0.5f) pos += LOG2F_ - s;
                else              neg += s + r - LOG2F_;
            }
        }
    }

    // ---- deterministic block reduction (reuse stage-0 smem) ----
    float* red = (float*)smem;
    __syncthreads();
    red[tid] = pos; red[256 + tid] = neg;
    __syncthreads();
#pragma unroll
    for (int s = 128; s > 0; s >>= 1) {
        if (tid < s) { red[tid] += red[tid + s]; red[256 + tid] += red[256 + tid + s]; }
        __syncthreads();
    }
    if (tid == 0) {
        int bid = blockIdx.y * gridDim.x + blockIdx.x;
        g_partials[bid]        = red[0];
        g_partials[NBLK + bid] = red[256];
    }
}

// ============================================================================
// Final reduction (deterministic double accumulation, vectorized loads)
// ============================================================================
__global__ void __launch_bounds__(512)
reduce_kernel(float* __restrict__ out)
{
    __shared__ double sp[512];
    __shared__ double sn[512];
    const int tid = threadIdx.x;
    double p = 0.0, n = 0.0;
#pragma unroll
    for (int i = tid; i < NBLK / 4; i += 512) {
        float4 vp = *(const float4*)(g_partials + i * 4);
        float4 vn = *(const float4*)(g_partials + NBLK + i * 4);
        p += (double)vp.x + (double)vp.y + (double)vp.z + (double)vp.w;
        n += (double)vn.x + (double)vn.y + (double)vn.z + (double)vn.w;
    }
    sp[tid] = p; sn[tid] = n;
    __syncthreads();
#pragma unroll
    for (int s = 256; s > 0; s >>= 1) {
        if (tid < s) { sp[tid] += sp[tid + s]; sn[tid] += sn[tid + s]; }
        __syncthreads();
    }
    if (tid == 0) {
        double E_pos = sp[0] / (double)NDRUGS;
        double E_neg = sn[0] / ((double)NDRUGS * (double)(NDRUGS - 1));
        out[0] = (float)(E_neg - E_pos);
    }
}

// ============================================================================
// launch
// ============================================================================
extern "C" void kernel_launch(void* const* d_in, const int* in_sizes, int n_in,
                              void* d_out, int out_size)
{
    const float* emb  = (const float*)d_in[0];
    const float* feat = (const float*)d_in[1];
    const float* adj  = (const float*)d_in[2];
    const float* g_w1 = (const float*)d_in[4];
    const float* g_b1 = (const float*)d_in[5];
    const float* g_w2 = (const float*)d_in[6];
    const float* g_b2 = (const float*)d_in[7];
    const float* g_w3 = (const float*)d_in[8];
    const float* g_b3 = (const float*)d_in[9];
    const float* g_ws = (const float*)d_in[10];
    const float* g_bs = (const float*)d_in[11];
    const float* l_w1 = (const float*)d_in[12];
    const float* l_b1 = (const float*)d_in[13];
    const float* l_w2 = (const float*)d_in[14];
    const float* l_b2 = (const float*)d_in[15];
    const float* l_w3 = (const float*)d_in[16];
    const float* l_b3 = (const float*)d_in[17];
    const float* l_ws = (const float*)d_in[18];
    const float* l_bs = (const float*)d_in[19];
    float* out = (float*)d_out;

    cudaFuncSetAttribute(score_kernel,
                         cudaFuncAttributeMaxDynamicSharedMemorySize, SM_SIZE);

    dim3 fgrid(NDRUGS / 16, 2);
    ff_kernel<<<fgrid, 256>>>(emb, feat,
                              g_w1, g_b1, g_w2, g_b2, g_w3, g_b3, g_ws, g_bs,
                              l_w1, l_b1, l_w2, l_b2, l_w3, l_b3, l_ws, l_bs);

    dim3 grid(NDRUGS / BT, NDRUGS / BT);
    score_kernel<<<grid, 256, SM_SIZE>>>(adj);

    reduce_kernel<<<1, 512>>>(out);
}

// round 9
// speedup vs baseline: 4.9313x; 1.6031x over previous
#include <cuda_runtime.h>
#include <cuda_bf16.h>
#include <math.h>
#include <stdint.h>

// Problem constants (fixed by the dataset)
#define NDRUGS 8192
#define KDIM   256
#define LOG2F_ 0.69314718055994531f

// ============================ device scratch ================================
__device__ __align__(1024) __nv_bfloat16 g_genc_bf[NDRUGS * KDIM];
__device__ __align__(1024) __nv_bfloat16 g_lenc_bf[NDRUGS * KDIM];
__device__ __align__(1024) __nv_bfloat16 g_wT[8 * KDIM * KDIM];   // bf16 W^T
__device__ __align__(1024) float g_ff_tmp[2 * NDRUGS * KDIM];     // per-encoder shortcut

#define BT   128
#define NBLK ((NDRUGS / BT) * (NDRUGS / BT))   // 64*64 = 4096
__device__ float g_partials[2 * NBLK];

// =========================== small PTX helpers ==============================
__device__ __forceinline__ uint32_t smem_u32(const void* p) {
    uint32_t a;
    asm("{ .reg .u64 t; cvta.to.shared.u64 t, %1; cvt.u32.u64 %0, t; }"
        : "=r"(a) : "l"(p));
    return a;
}
__device__ __forceinline__ void cp_async16(uint32_t dst, const void* src) {
    asm volatile("cp.async.cg.shared.global [%0], [%1], 16;"
                 :: "r"(dst), "l"(src) : "memory");
}
__device__ __forceinline__ void cp_async_commit() {
    asm volatile("cp.async.commit_group;" ::: "memory");
}
template <int N>
__device__ __forceinline__ void cp_async_wait() {
    asm volatile("cp.async.wait_group %0;" :: "n"(N) : "memory");
}
__device__ __forceinline__ void prefetch_l2(const void* p) {
    asm volatile("prefetch.global.L2 [%0];" :: "l"(p));
}
__device__ __forceinline__ void ldmatrix_x4(uint32_t& r0, uint32_t& r1,
                                            uint32_t& r2, uint32_t& r3,
                                            uint32_t addr) {
    asm volatile("ldmatrix.sync.aligned.m8n8.x4.shared.b16 {%0,%1,%2,%3}, [%4];"
                 : "=r"(r0), "=r"(r1), "=r"(r2), "=r"(r3) : "r"(addr));
}
__device__ __forceinline__ void mma_bf16(float& d0, float& d1, float& d2, float& d3,
                                         uint32_t a0, uint32_t a1, uint32_t a2,
                                         uint32_t a3, uint32_t b0, uint32_t b1) {
    asm volatile(
        "mma.sync.aligned.m16n8k16.row.col.f32.bf16.bf16.f32 "
        "{%0,%1,%2,%3}, {%4,%5,%6,%7}, {%8,%9}, {%0,%1,%2,%3};"
        : "+f"(d0), "+f"(d1), "+f"(d2), "+f"(d3)
        : "r"(a0), "r"(a1), "r"(a2), "r"(a3), "r"(b0), "r"(b1));
}
__device__ __forceinline__ uint32_t pack_bf2(float a, float b) {
    __nv_bfloat162 h = __floats2bfloat162_rn(a, b);
    return *(uint32_t*)&h;
}

// ============================================================================
// Weight transpose + bf16 convert: g_wT[mat][n*256+k] = bf16(w_mat[k*256+n])
// mat order: 0..3 = g_w1,g_w2,g_w3,g_ws ; 4..7 = l_w1,l_w2,l_w3,l_ws
// ============================================================================
__global__ void __launch_bounds__(256)
wT_kernel(const float* __restrict__ m0, const float* __restrict__ m1,
          const float* __restrict__ m2, const float* __restrict__ m3,
          const float* __restrict__ m4, const float* __restrict__ m5,
          const float* __restrict__ m6, const float* __restrict__ m7)
{
    const float* srcs[8] = {m0, m1, m2, m3, m4, m5, m6, m7};
    const float* w = srcs[blockIdx.y];
    __nv_bfloat16* dst = g_wT + (size_t)blockIdx.y * KDIM * KDIM;

    __shared__ float t[64][65];
    const int tid = threadIdx.x;
    const int n0 = (blockIdx.x & 3) * 64;
    const int k0 = (blockIdx.x >> 2) * 64;

#pragma unroll
    for (int i = tid; i < 64 * 64; i += 256) {
        int r = i >> 6, c = i & 63;
        t[r][c] = w[(size_t)(k0 + r) * KDIM + n0 + c];
    }
    __syncthreads();
#pragma unroll
    for (int i = tid; i < 64 * 64; i += 256) {
        int r = i >> 6, c = i & 63;
        dst[(size_t)(n0 + r) * KDIM + k0 + c] = __float2bfloat16(t[c][r]);
    }
}

// ============================================================================
// Fused FF encoder via mma.sync: 128 rows/CTA through all 4 matmuls.
// 512 threads = 16 warps of 32x64 (M=128, N=256).
// ============================================================================
#define FF_LDX  264
#define FF_LDW  72
#define FF_X0   0
#define FF_X1   67584
#define FF_W    135168
#define FF_WSTG 36864
#define FF_SMEM 208896

// mode 0: out = A@W + b                   -> tmp (fp32 global)
// mode 1: out = relu(A@W + b)             -> Xdst (bf16 smem)
// mode 2: out = relu(A@W + b) + tmp       -> gout (bf16 global)
__device__ __forceinline__ void ff_gemm(
    char* smem, uint32_t s_base, uint32_t xsrc, uint32_t xdst, int mode,
    const __nv_bfloat16* __restrict__ wmat, const float* __restrict__ bias,
    float* __restrict__ tmp, __nv_bfloat16* __restrict__ gout, int row0,
    int tid, int mrow, int ncol, int gid, int tig,
    uint32_t aL, uint32_t bL)
{
    float acc[2][8][4];
#pragma unroll
    for (int mt = 0; mt < 2; mt++)
#pragma unroll
        for (int nt = 0; nt < 8; nt++)
#pragma unroll
            for (int q = 0; q < 4; q++) acc[mt][nt][q] = 0.f;

    const int wrow = tid >> 3;
    const int wkq  = (tid & 7) * 8;
    auto issueW = [&](int kc, int st) {
        const uint32_t w_s = s_base + FF_W + st * FF_WSTG;
#pragma unroll
        for (int it = 0; it < 4; it++) {
            int row = wrow + it * 64;
            cp_async16(w_s + (uint32_t)(row * FF_LDW + wkq) * 2,
                       wmat + (size_t)row * KDIM + kc * 64 + wkq);
        }
        cp_async_commit();
    };

    issueW(0, 0);
#pragma unroll 1
    for (int kc = 0; kc < 4; kc++) {
        const int st = kc & 1;
        cp_async_wait<0>();
        __syncthreads();
        if (kc < 3) issueW(kc + 1, st ^ 1);

        const uint32_t a_s = s_base + xsrc + aL;
        const uint32_t b_s = s_base + FF_W + st * FF_WSTG + bL;
#pragma unroll
        for (int ks = 0; ks < 4; ks++) {
            const uint32_t ak = (uint32_t)((kc * 64 + ks * 16) * 2);
            const uint32_t bk = (uint32_t)(ks * 16 * 2);
            uint32_t bfr[8][2];
#pragma unroll
            for (int ntp = 0; ntp < 4; ntp++) {
                uint32_t r0, r1, r2, r3;
                ldmatrix_x4(r0, r1, r2, r3,
                            b_s + (uint32_t)(ntp * 16 * FF_LDW) * 2 + bk);
                bfr[2 * ntp][0]     = r0; bfr[2 * ntp][1]     = r1;
                bfr[2 * ntp + 1][0] = r2; bfr[2 * ntp + 1][1] = r3;
            }
#pragma unroll
            for (int mt = 0; mt < 2; mt++) {
                uint32_t a0, a1, a2, a3;
                ldmatrix_x4(a0, a1, a2, a3,
                            a_s + (uint32_t)(mt * 16 * FF_LDX) * 2 + ak);
#pragma unroll
                for (int nt = 0; nt < 8; nt++)
                    mma_bf16(acc[mt][nt][0], acc[mt][nt][1],
                             acc[mt][nt][2], acc[mt][nt][3],
                             a0, a1, a2, a3, bfr[nt][0], bfr[nt][1]);
            }
        }
    }

    // ---- epilogue ----
#pragma unroll
    for (int mt = 0; mt < 2; mt++) {
        const int r = mrow + mt * 16 + gid;
#pragma unroll
        for (int nt = 0; nt < 8; nt++) {
            const int c0 = ncol + nt * 8 + tig * 2;
            float bv0 = __ldg(bias + c0), bv1 = __ldg(bias + c0 + 1);
            float d0 = acc[mt][nt][0] + bv0, d1 = acc[mt][nt][1] + bv1;
            float d2 = acc[mt][nt][2] + bv0, d3 = acc[mt][nt][3] + bv1;
            if (mode == 0) {
                float2 lo = {d0, d1}, hi = {d2, d3};
                *(float2*)(tmp + (size_t)(row0 + r) * KDIM + c0) = lo;
                *(float2*)(tmp + (size_t)(row0 + r + 8) * KDIM + c0) = hi;
            } else if (mode == 1) {
                uint32_t lo = pack_bf2(fmaxf(d0, 0.f), fmaxf(d1, 0.f));
                uint32_t hi = pack_bf2(fmaxf(d2, 0.f), fmaxf(d3, 0.f));
                *(uint32_t*)(smem + xdst + (uint32_t)(r * FF_LDX + c0) * 2) = lo;
                *(uint32_t*)(smem + xdst + (uint32_t)((r + 8) * FF_LDX + c0) * 2) = hi;
            } else {
                float2 t0 = *(const float2*)(tmp + (size_t)(row0 + r) * KDIM + c0);
                float2 t1 = *(const float2*)(tmp + (size_t)(row0 + r + 8) * KDIM + c0);
                uint32_t lo = pack_bf2(fmaxf(d0, 0.f) + t0.x, fmaxf(d1, 0.f) + t0.y);
                uint32_t hi = pack_bf2(fmaxf(d2, 0.f) + t1.x, fmaxf(d3, 0.f) + t1.y);
                *(uint32_t*)(gout + (size_t)(row0 + r) * KDIM + c0) = lo;
                *(uint32_t*)(gout + (size_t)(row0 + r + 8) * KDIM + c0) = hi;
            }
        }
    }
}

__global__ void __launch_bounds__(512, 1)
ff_mma_kernel(const float* __restrict__ xg, const float* __restrict__ xl,
              const float* __restrict__ gb1, const float* __restrict__ gb2,
              const float* __restrict__ gb3, const float* __restrict__ gbs,
              const float* __restrict__ lb1, const float* __restrict__ lb2,
              const float* __restrict__ lb3, const float* __restrict__ lbs)
{
    extern __shared__ char smem[];
    const uint32_t s_base = smem_u32(smem);

    const int tid  = threadIdx.x;
    const int lane = tid & 31;
    const int warp = tid >> 5;
    const int gid  = lane >> 2, tig = lane & 3;
    const int mrow = (warp >> 2) * 32;
    const int ncol = (warp & 3) * 64;

    const int which = blockIdx.y;
    const int row0  = blockIdx.x * 128;

    const float* x  = which ? xl : xg;
    const __nv_bfloat16* wT = g_wT + (size_t)which * 4 * KDIM * KDIM;
    const float* b1 = which ? lb1 : gb1;
    const float* b2 = which ? lb2 : gb2;
    const float* b3 = which ? lb3 : gb3;
    const float* bs = which ? lbs : gbs;
    __nv_bfloat16* gout = which ? g_lenc_bf : g_genc_bf;
    float* tmp = g_ff_tmp + (size_t)which * NDRUGS * KDIM;   // per-encoder!

    // ---- convert input fp32 -> bf16 into X0 ----
#pragma unroll
    for (int it = 0; it < 16; it++) {
        int c   = tid + it * 512;
        int row = c >> 6;
        int kq  = (c & 63) * 4;
        float4 v = *(const float4*)(x + (size_t)(row0 + row) * KDIM + kq);
        uint2 u;
        u.x = pack_bf2(v.x, v.y);
        u.y = pack_bf2(v.z, v.w);
        *(uint2*)(smem + FF_X0 + (uint32_t)(row * FF_LDX + kq) * 2) = u;
    }
    __syncthreads();

    const uint32_t aL = (uint32_t)((mrow + (lane & 7) + ((lane >> 3) & 1) * 8)
                                   * FF_LDX + (lane >> 4) * 8) * 2;
    const uint32_t bL = (uint32_t)((ncol + (lane & 7) + (lane >> 4) * 8)
                                   * FF_LDW + ((lane >> 3) & 1) * 8) * 2;

    // shortcut: tmp = X0 @ WsT + bs
    ff_gemm(smem, s_base, FF_X0, 0, 0, wT + 3 * KDIM * KDIM, bs, tmp, gout, row0,
            tid, mrow, ncol, gid, tig, aL, bL);
    // h1 = relu(X0 @ W1T + b1) -> X1
    ff_gemm(smem, s_base, FF_X0, FF_X1, 1, wT + 0 * KDIM * KDIM, b1, tmp, gout, row0,
            tid, mrow, ncol, gid, tig, aL, bL);
    // h2 = relu(X1 @ W2T + b2) -> X0
    ff_gemm(smem, s_base, FF_X1, FF_X0, 1, wT + 1 * KDIM * KDIM, b2, tmp, gout, row0,
            tid, mrow, ncol, gid, tig, aL, bL);
    // out = relu(X0 @ W3T + b3) + tmp -> global bf16
    ff_gemm(smem, s_base, FF_X0, 0, 2, wT + 2 * KDIM * KDIM, b3, tmp, gout, row0,
            tid, mrow, ncol, gid, tig, aL, bL);
}

// ============================================================================
// Score GEMM: mma.sync bf16, 128x128 CTA tile, 4 K-chunks of 64, 2-stage
// cp.async pipeline, ldmatrix fragment loads, fused JSD epilogue.
// ============================================================================
#define LDK     72
#define STG_A   (128 * LDK * 2)
#define STG_SZ  (2 * STG_A)
#define SM_SIZE (2 * STG_SZ)

__global__ void __launch_bounds__(256, 2)
score_kernel(const float* __restrict__ adj)
{
    extern __shared__ char smem[];
    const uint32_t s_base = smem_u32(smem);

    const int tid  = threadIdx.x;
    const int lane = tid & 31;
    const int warp = tid >> 5;
    const int gid  = lane >> 2;
    const int tig  = lane & 3;
    const int mrow = (warp >> 1) * 32;
    const int ncol = (warp & 1) * 64;

    const int i0 = blockIdx.y * BT;
    const int j0 = blockIdx.x * BT;

#pragma unroll
    for (int t = tid; t < 512; t += 256) {
        int row = t >> 2, seg = t & 3;
        prefetch_l2(adj + (size_t)(i0 + row) * NDRUGS + j0 + seg * 32);
    }

    const int lrow = tid >> 3;
    const int lkq  = (tid & 7) * 8;
    auto issue = [&](int kc, int st) {
        const uint32_t a_s = s_base + st * STG_SZ;
        const uint32_t b_s = a_s + STG_A;
#pragma unroll
        for (int it = 0; it < 4; it++) {
            int row = lrow + it * 32;
            uint32_t soff = (uint32_t)(row * LDK + lkq) * 2;
            const size_t goff = (size_t)row * KDIM + kc * 64 + lkq;
            cp_async16(a_s + soff, g_lenc_bf + (size_t)i0 * KDIM + goff);
            cp_async16(b_s + soff, g_genc_bf + (size_t)j0 * KDIM + goff);
        }
        cp_async_commit();
    };

    const int a_row  = mrow + (lane & 7) + ((lane >> 3) & 1) * 8;
    const int a_koff = (lane >> 4) * 8;
    const uint32_t a_lane = (uint32_t)(a_row * LDK + a_koff) * 2;
    const int b_row  = ncol + (lane & 7) + (lane >> 4) * 8;
    const int b_koff = ((lane >> 3) & 1) * 8;
    const uint32_t b_lane = (uint32_t)(b_row * LDK + b_koff) * 2;

    float acc[2][8][4];
#pragma unroll
    for (int mt = 0; mt < 2; mt++)
#pragma unroll
        for (int nt = 0; nt < 8; nt++)
#pragma unroll
            for (int q = 0; q < 4; q++) acc[mt][nt][q] = 0.f;

    issue(0, 0);

#pragma unroll 1
    for (int kc = 0; kc < 4; kc++) {
        const int st = kc & 1;
        if (kc < 3) issue(kc + 1, st ^ 1);
        if (kc < 3) cp_async_wait<1>(); else cp_async_wait<0>();
        __syncthreads();

        const uint32_t a_s = s_base + st * STG_SZ + a_lane;
        const uint32_t b_s = s_base + st * STG_SZ + STG_A + b_lane;

#pragma unroll
        for (int ks = 0; ks < 4; ks++) {
            const uint32_t k0b = (uint32_t)(ks * 16) * 2;
            uint32_t bfr[8][2];
#pragma unroll
            for (int ntp = 0; ntp < 4; ntp++) {
                uint32_t r0, r1, r2, r3;
                ldmatrix_x4(r0, r1, r2, r3,
                            b_s + (uint32_t)(ntp * 16 * LDK) * 2 + k0b);
                bfr[2 * ntp][0]     = r0; bfr[2 * ntp][1]     = r1;
                bfr[2 * ntp + 1][0] = r2; bfr[2 * ntp + 1][1] = r3;
            }
#pragma unroll
            for (int mt = 0; mt < 2; mt++) {
                uint32_t a0, a1, a2, a3;
                ldmatrix_x4(a0, a1, a2, a3,
                            a_s + (uint32_t)(mt * 16 * LDK) * 2 + k0b);
#pragma unroll
                for (int nt = 0; nt < 8; nt++)
                    mma_bf16(acc[mt][nt][0], acc[mt][nt][1],
                             acc[mt][nt][2], acc[mt][nt][3],
                             a0, a1, a2, a3, bfr[nt][0], bfr[nt][1]);
            }
        }
        __syncthreads();
    }

    float pos = 0.f, neg = 0.f;
#pragma unroll
    for (int mt = 0; mt < 2; mt++) {
        const int r0 = i0 + mrow + mt * 16 + gid;
#pragma unroll
        for (int nt = 0; nt < 8; nt++) {
            const int c0 = j0 + ncol + nt * 8 + tig * 2;
            float2 alo = __ldg((const float2*)(adj + (size_t)r0 * NDRUGS + c0));
            float2 ahi = __ldg((const float2*)(adj + (size_t)(r0 + 8) * NDRUGS + c0));
            float aa[4] = {alo.x, alo.y, ahi.x, ahi.y};
#pragma unroll
            for (int q = 0; q < 4; q++) {
                float r = acc[mt][nt][q];
                float s = fmaxf(-r, 0.f) + __logf(1.f + __expf(-fabsf(r)));
                if (aa[q] > 0.5f) pos += LOG2F_ - s;
                else              neg += s + r - LOG2F_;
            }
        }
    }

    float* red = (float*)smem;
    __syncthreads();
    red[tid] = pos; red[256 + tid] = neg;
    __syncthreads();
#pragma unroll
    for (int s = 128; s > 0; s >>= 1) {
        if (tid < s) { red[tid] += red[tid + s]; red[256 + tid] += red[256 + tid + s]; }
        __syncthreads();
    }
    if (tid == 0) {
        int bid = blockIdx.y * gridDim.x + blockIdx.x;
        g_partials[bid]        = red[0];
        g_partials[NBLK + bid] = red[256];
    }
}

// ============================================================================
// Final reduction (deterministic double accumulation)
// ============================================================================
__global__ void __launch_bounds__(512)
reduce_kernel(float* __restrict__ out)
{
    __shared__ double sp[512];
    __shared__ double sn[512];
    const int tid = threadIdx.x;
    double p = 0.0, n = 0.0;
#pragma unroll
    for (int i = tid; i < NBLK / 4; i += 512) {
        float4 vp = *(const float4*)(g_partials + i * 4);
        float4 vn = *(const float4*)(g_partials + NBLK + i * 4);
        p += (double)vp.x + (double)vp.y + (double)vp.z + (double)vp.w;
        n += (double)vn.x + (double)vn.y + (double)vn.z + (double)vn.w;
    }
    sp[tid] = p; sn[tid] = n;
    __syncthreads();
#pragma unroll
    for (int s = 256; s > 0; s >>= 1) {
        if (tid < s) { sp[tid] += sp[tid + s]; sn[tid] += sn[tid + s]; }
        __syncthreads();
    }
    if (tid == 0) {
        double E_pos = sp[0] / (double)NDRUGS;
        double E_neg = sn[0] / ((double)NDRUGS * (double)(NDRUGS - 1));
        out[0] = (float)(E_neg - E_pos);
    }
}

// ============================================================================
// launch
// ============================================================================
extern "C" void kernel_launch(void* const* d_in, const int* in_sizes, int n_in,
                              void* d_out, int out_size)
{
    const float* emb  = (const float*)d_in[0];
    const float* feat = (const float*)d_in[1];
    const float* adj  = (const float*)d_in[2];
    const float* g_w1 = (const float*)d_in[4];
    const float* g_b1 = (const float*)d_in[5];
    const float* g_w2 = (const float*)d_in[6];
    const float* g_b2 = (const float*)d_in[7];
    const float* g_w3 = (const float*)d_in[8];
    const float* g_b3 = (const float*)d_in[9];
    const float* g_ws = (const float*)d_in[10];
    const float* g_bs = (const float*)d_in[11];
    const float* l_w1 = (const float*)d_in[12];
    const float* l_b1 = (const float*)d_in[13];
    const float* l_w2 = (const float*)d_in[14];
    const float* l_b2 = (const float*)d_in[15];
    const float* l_w3 = (const float*)d_in[16];
    const float* l_b3 = (const float*)d_in[17];
    const float* l_ws = (const float*)d_in[18];
    const float* l_bs = (const float*)d_in[19];
    float* out = (float*)d_out;

    cudaFuncSetAttribute(score_kernel,
                         cudaFuncAttributeMaxDynamicSharedMemorySize, SM_SIZE);
    cudaFuncSetAttribute(ff_mma_kernel,
                         cudaFuncAttributeMaxDynamicSharedMemorySize, FF_SMEM);

    dim3 tgrid(16, 8);
    wT_kernel<<<tgrid, 256>>>(g_w1, g_w2, g_w3, g_ws, l_w1, l_w2, l_w3, l_ws);

    dim3 fgrid(NDRUGS / 128, 2);
    ff_mma_kernel<<<fgrid, 512, FF_SMEM>>>(emb, feat,
                                           g_b1, g_b2, g_b3, g_bs,
                                           l_b1, l_b2, l_b3, l_bs);

    dim3 grid(NDRUGS / BT, NDRUGS / BT);
    score_kernel<<<grid, 256, SM_SIZE>>>(adj);

    reduce_kernel<<<1, 512>>>(out);
}

// round 10
// speedup vs baseline: 6.8333x; 1.3857x over previous
#include <cuda_runtime.h>
#include <cuda_bf16.h>
#include <math.h>
#include <stdint.h>

// Problem constants (fixed by the dataset)
#define NDRUGS 8192
#define KDIM   256
#define LOG2F_ 0.69314718055994531f

// ============================ device scratch ================================
__device__ __align__(1024) __nv_bfloat16 g_genc_bf[NDRUGS * KDIM];
__device__ __align__(1024) __nv_bfloat16 g_lenc_bf[NDRUGS * KDIM];
__device__ __align__(1024) __nv_bfloat16 g_wT[8 * KDIM * KDIM];   // bf16 W^T
__device__ __align__(1024) float g_ff_tmp[2 * NDRUGS * KDIM];     // per-encoder shortcut

#define BT   128
#define NBLK ((NDRUGS / BT) * (NDRUGS / BT))   // 64*64 = 4096
__device__ float g_partials[2 * NBLK];
__device__ unsigned int g_done;                // zero-init; self-resetting

// =========================== small PTX helpers ==============================
__device__ __forceinline__ uint32_t smem_u32(const void* p) {
    uint32_t a;
    asm("{ .reg .u64 t; cvta.to.shared.u64 t, %1; cvt.u32.u64 %0, t; }"
        : "=r"(a) : "l"(p));
    return a;
}
__device__ __forceinline__ void cp_async16(uint32_t dst, const void* src) {
    asm volatile("cp.async.cg.shared.global [%0], [%1], 16;"
                 :: "r"(dst), "l"(src) : "memory");
}
__device__ __forceinline__ void cp_async_commit() {
    asm volatile("cp.async.commit_group;" ::: "memory");
}
template <int N>
__device__ __forceinline__ void cp_async_wait() {
    asm volatile("cp.async.wait_group %0;" :: "n"(N) : "memory");
}
__device__ __forceinline__ void prefetch_l2(const void* p) {
    asm volatile("prefetch.global.L2 [%0];" :: "l"(p));
}
__device__ __forceinline__ void ldmatrix_x4(uint32_t& r0, uint32_t& r1,
                                            uint32_t& r2, uint32_t& r3,
                                            uint32_t addr) {
    asm volatile("ldmatrix.sync.aligned.m8n8.x4.shared.b16 {%0,%1,%2,%3}, [%4];"
                 : "=r"(r0), "=r"(r1), "=r"(r2), "=r"(r3) : "r"(addr));
}
__device__ __forceinline__ void mma_bf16(float& d0, float& d1, float& d2, float& d3,
                                         uint32_t a0, uint32_t a1, uint32_t a2,
                                         uint32_t a3, uint32_t b0, uint32_t b1) {
    asm volatile(
        "mma.sync.aligned.m16n8k16.row.col.f32.bf16.bf16.f32 "
        "{%0,%1,%2,%3}, {%4,%5,%6,%7}, {%8,%9}, {%0,%1,%2,%3};"
        : "+f"(d0), "+f"(d1), "+f"(d2), "+f"(d3)
        : "r"(a0), "r"(a1), "r"(a2), "r"(a3), "r"(b0), "r"(b1));
}
__device__ __forceinline__ uint32_t pack_bf2(float a, float b) {
    __nv_bfloat162 h = __floats2bfloat162_rn(a, b);
    return *(uint32_t*)&h;
}

// ============================================================================
// Weight transpose + bf16 convert: g_wT[mat][n*256+k] = bf16(w_mat[k*256+n])
// mat order: 0..3 = g_w1,g_w2,g_w3,g_ws ; 4..7 = l_w1,l_w2,l_w3,l_ws
// ============================================================================
__global__ void __launch_bounds__(256)
wT_kernel(const float* __restrict__ m0, const float* __restrict__ m1,
          const float* __restrict__ m2, const float* __restrict__ m3,
          const float* __restrict__ m4, const float* __restrict__ m5,
          const float* __restrict__ m6, const float* __restrict__ m7)
{
    const float* srcs[8] = {m0, m1, m2, m3, m4, m5, m6, m7};
    const float* w = srcs[blockIdx.y];
    __nv_bfloat16* dst = g_wT + (size_t)blockIdx.y * KDIM * KDIM;

    __shared__ float t[64][65];
    const int tid = threadIdx.x;
    const int n0 = (blockIdx.x & 3) * 64;
    const int k0 = (blockIdx.x >> 2) * 64;

#pragma unroll
    for (int i = tid; i < 64 * 64; i += 256) {
        int r = i >> 6, c = i & 63;
        t[r][c] = w[(size_t)(k0 + r) * KDIM + n0 + c];
    }
    __syncthreads();
#pragma unroll
    for (int i = tid; i < 64 * 64; i += 256) {
        int r = i >> 6, c = i & 63;
        dst[(size_t)(n0 + r) * KDIM + k0 + c] = __float2bfloat16(t[c][r]);
    }
}

// ============================================================================
// Fused FF encoder via mma.sync: M=64 rows/CTA, 256 threads (8 warps 32x64),
// 2 CTAs/SM. W streamed as 32-col chunks, double-buffered.
// SMEM: X0 (64x264 bf16 = 33792) + X1 (33792) + W 2x(256x40 bf16 = 20480)
//     = 108544 B
// ============================================================================
#define FF_LDX  264
#define FF_LDW  40
#define FF_X0   0
#define FF_X1   33792
#define FF_W    67584
#define FF_WSTG 20480
#define FF_SMEM 108544

// mode 0: out = A@W + b                   -> tmp (fp32 global)
// mode 1: out = relu(A@W + b)             -> Xdst (bf16 smem)
// mode 2: out = relu(A@W + b) + tmp       -> gout (bf16 global)
__device__ __forceinline__ void ff_gemm(
    char* smem, uint32_t s_base, uint32_t xsrc, uint32_t xdst, int mode,
    const __nv_bfloat16* __restrict__ wmat, const float* __restrict__ bias,
    float* __restrict__ tmp, __nv_bfloat16* __restrict__ gout, int row0,
    int tid, int mrow, int ncol, int gid, int tig,
    uint32_t aL, uint32_t bL)
{
    float acc[2][8][4];
#pragma unroll
    for (int mt = 0; mt < 2; mt++)
#pragma unroll
        for (int nt = 0; nt < 8; nt++)
#pragma unroll
            for (int q = 0; q < 4; q++) acc[mt][nt][q] = 0.f;

    // W chunk: 256 rows x 32 bf16 = 16 KB = 1024 16B-chunks, 4 per thread
    const int wrow = tid >> 2;          // +it*64 -> 0..255
    const int wkq  = (tid & 3) * 8;     // bf16 col 0,8,16,24
    auto issueW = [&](int kc, int st) {
        const uint32_t w_s = s_base + FF_W + st * FF_WSTG;
#pragma unroll
        for (int it = 0; it < 4; it++) {
            int row = wrow + it * 64;
            cp_async16(w_s + (uint32_t)(row * FF_LDW + wkq) * 2,
                       wmat + (size_t)row * KDIM + kc * 32 + wkq);
        }
        cp_async_commit();
    };

    issueW(0, 0);
#pragma unroll 1
    for (int kc = 0; kc < 8; kc++) {
        const int st = kc & 1;
        if (kc < 7) issueW(kc + 1, st ^ 1);
        if (kc < 7) cp_async_wait<1>(); else cp_async_wait<0>();
        __syncthreads();

        const uint32_t a_s = s_base + xsrc + aL;
        const uint32_t b_s = s_base + FF_W + st * FF_WSTG + bL;
#pragma unroll
        for (int ks = 0; ks < 2; ks++) {
            const uint32_t ak = (uint32_t)((kc * 32 + ks * 16) * 2);
            const uint32_t bk = (uint32_t)(ks * 16 * 2);
            uint32_t bfr[8][2];
#pragma unroll
            for (int ntp = 0; ntp < 4; ntp++) {
                uint32_t r0, r1, r2, r3;
                ldmatrix_x4(r0, r1, r2, r3,
                            b_s + (uint32_t)(ntp * 16 * FF_LDW) * 2 + bk);
                bfr[2 * ntp][0]     = r0; bfr[2 * ntp][1]     = r1;
                bfr[2 * ntp + 1][0] = r2; bfr[2 * ntp + 1][1] = r3;
            }
#pragma unroll
            for (int mt = 0; mt < 2; mt++) {
                uint32_t a0, a1, a2, a3;
                ldmatrix_x4(a0, a1, a2, a3,
                            a_s + (uint32_t)(mt * 16 * FF_LDX) * 2 + ak);
#pragma unroll
                for (int nt = 0; nt < 8; nt++)
                    mma_bf16(acc[mt][nt][0], acc[mt][nt][1],
                             acc[mt][nt][2], acc[mt][nt][3],
                             a0, a1, a2, a3, bfr[nt][0], bfr[nt][1]);
            }
        }
        __syncthreads();
    }

    // ---- epilogue ----
#pragma unroll
    for (int mt = 0; mt < 2; mt++) {
        const int r = mrow + mt * 16 + gid;          // local row < 64
#pragma unroll
        for (int nt = 0; nt < 8; nt++) {
            const int c0 = ncol + nt * 8 + tig * 2;
            float bv0 = __ldg(bias + c0), bv1 = __ldg(bias + c0 + 1);
            float d0 = acc[mt][nt][0] + bv0, d1 = acc[mt][nt][1] + bv1;
            float d2 = acc[mt][nt][2] + bv0, d3 = acc[mt][nt][3] + bv1;
            if (mode == 0) {
                float2 lo = {d0, d1}, hi = {d2, d3};
                *(float2*)(tmp + (size_t)(row0 + r) * KDIM + c0) = lo;
                *(float2*)(tmp + (size_t)(row0 + r + 8) * KDIM + c0) = hi;
            } else if (mode == 1) {
                uint32_t lo = pack_bf2(fmaxf(d0, 0.f), fmaxf(d1, 0.f));
                uint32_t hi = pack_bf2(fmaxf(d2, 0.f), fmaxf(d3, 0.f));
                *(uint32_t*)(smem + xdst + (uint32_t)(r * FF_LDX + c0) * 2) = lo;
                *(uint32_t*)(smem + xdst + (uint32_t)((r + 8) * FF_LDX + c0) * 2) = hi;
            } else {
                float2 t0 = *(const float2*)(tmp + (size_t)(row0 + r) * KDIM + c0);
                float2 t1 = *(const float2*)(tmp + (size_t)(row0 + r + 8) * KDIM + c0);
                uint32_t lo = pack_bf2(fmaxf(d0, 0.f) + t0.x, fmaxf(d1, 0.f) + t0.y);
                uint32_t hi = pack_bf2(fmaxf(d2, 0.f) + t1.x, fmaxf(d3, 0.f) + t1.y);
                *(uint32_t*)(gout + (size_t)(row0 + r) * KDIM + c0) = lo;
                *(uint32_t*)(gout + (size_t)(row0 + r + 8) * KDIM + c0) = hi;
            }
        }
    }
}

__global__ void __launch_bounds__(256, 2)
ff_mma_kernel(const float* __restrict__ xg, const float* __restrict__ xl,
              const float* __restrict__ gb1, const float* __restrict__ gb2,
              const float* __restrict__ gb3, const float* __restrict__ gbs,
              const float* __restrict__ lb1, const float* __restrict__ lb2,
              const float* __restrict__ lb3, const float* __restrict__ lbs)
{
    extern __shared__ char smem[];
    const uint32_t s_base = smem_u32(smem);

    const int tid  = threadIdx.x;
    const int lane = tid & 31;
    const int warp = tid >> 5;
    const int gid  = lane >> 2, tig = lane & 3;
    const int mrow = (warp >> 2) * 32;   // 0..32
    const int ncol = (warp & 3) * 64;    // 0..192

    const int which = blockIdx.y;
    const int row0  = blockIdx.x * 64;

    const float* x  = which ? xl : xg;
    const __nv_bfloat16* wT = g_wT + (size_t)which * 4 * KDIM * KDIM;
    const float* b1 = which ? lb1 : gb1;
    const float* b2 = which ? lb2 : gb2;
    const float* b3 = which ? lb3 : gb3;
    const float* bs = which ? lbs : gbs;
    __nv_bfloat16* gout = which ? g_lenc_bf : g_genc_bf;
    float* tmp = g_ff_tmp + (size_t)which * NDRUGS * KDIM;

    // ---- convert input fp32 -> bf16 into X0 (64x256 = 4096 float4) ----
#pragma unroll
    for (int it = 0; it < 16; it++) {
        int c   = tid + it * 256;
        int row = c >> 6;
        int kq  = (c & 63) * 4;
        float4 v = *(const float4*)(x + (size_t)(row0 + row) * KDIM + kq);
        uint2 u;
        u.x = pack_bf2(v.x, v.y);
        u.y = pack_bf2(v.z, v.w);
        *(uint2*)(smem + FF_X0 + (uint32_t)(row * FF_LDX + kq) * 2) = u;
    }
    __syncthreads();

    const uint32_t aL = (uint32_t)((mrow + (lane & 7) + ((lane >> 3) & 1) * 8)
                                   * FF_LDX + (lane >> 4) * 8) * 2;
    const uint32_t bL = (uint32_t)((ncol + (lane & 7) + (lane >> 4) * 8)
                                   * FF_LDW + ((lane >> 3) & 1) * 8) * 2;

    // shortcut: tmp = X0 @ WsT + bs
    ff_gemm(smem, s_base, FF_X0, 0, 0, wT + 3 * KDIM * KDIM, bs, tmp, gout, row0,
            tid, mrow, ncol, gid, tig, aL, bL);
    // h1 = relu(X0 @ W1T + b1) -> X1
    ff_gemm(smem, s_base, FF_X0, FF_X1, 1, wT + 0 * KDIM * KDIM, b1, tmp, gout, row0,
            tid, mrow, ncol, gid, tig, aL, bL);
    // h2 = relu(X1 @ W2T + b2) -> X0
    ff_gemm(smem, s_base, FF_X1, FF_X0, 1, wT + 1 * KDIM * KDIM, b2, tmp, gout, row0,
            tid, mrow, ncol, gid, tig, aL, bL);
    // out = relu(X0 @ W3T + b3) + tmp -> global bf16
    ff_gemm(smem, s_base, FF_X0, 0, 2, wT + 2 * KDIM * KDIM, b3, tmp, gout, row0,
            tid, mrow, ncol, gid, tig, aL, bL);
}

// ============================================================================
// Score GEMM: mma.sync bf16, 128x128 CTA tile, 4 K-chunks of 64, 2-stage
// cp.async pipeline, ldmatrix, fused JSD epilogue + last-block final reduce.
// ============================================================================
#define LDK     72
#define STG_A   (128 * LDK * 2)
#define STG_SZ  (2 * STG_A)
#define SM_SIZE (2 * STG_SZ)

__global__ void __launch_bounds__(256, 2)
score_kernel(const float* __restrict__ adj, float* __restrict__ out)
{
    extern __shared__ char smem[];
    const uint32_t s_base = smem_u32(smem);

    const int tid  = threadIdx.x;
    const int lane = tid & 31;
    const int warp = tid >> 5;
    const int gid  = lane >> 2;
    const int tig  = lane & 3;
    const int mrow = (warp >> 1) * 32;
    const int ncol = (warp & 1) * 64;

    const int i0 = blockIdx.y * BT;
    const int j0 = blockIdx.x * BT;

#pragma unroll
    for (int t = tid; t < 512; t += 256) {
        int row = t >> 2, seg = t & 3;
        prefetch_l2(adj + (size_t)(i0 + row) * NDRUGS + j0 + seg * 32);
    }

    const int lrow = tid >> 3;
    const int lkq  = (tid & 7) * 8;
    auto issue = [&](int kc, int st) {
        const uint32_t a_s = s_base + st * STG_SZ;
        const uint32_t b_s = a_s + STG_A;
#pragma unroll
        for (int it = 0; it < 4; it++) {
            int row = lrow + it * 32;
            uint32_t soff = (uint32_t)(row * LDK + lkq) * 2;
            const size_t goff = (size_t)row * KDIM + kc * 64 + lkq;
            cp_async16(a_s + soff, g_lenc_bf + (size_t)i0 * KDIM + goff);
            cp_async16(b_s + soff, g_genc_bf + (size_t)j0 * KDIM + goff);
        }
        cp_async_commit();
    };

    const int a_row  = mrow + (lane & 7) + ((lane >> 3) & 1) * 8;
    const int a_koff = (lane >> 4) * 8;
    const uint32_t a_lane = (uint32_t)(a_row * LDK + a_koff) * 2;
    const int b_row  = ncol + (lane & 7) + (lane >> 4) * 8;
    const int b_koff = ((lane >> 3) & 1) * 8;
    const uint32_t b_lane = (uint32_t)(b_row * LDK + b_koff) * 2;

    float acc[2][8][4];
#pragma unroll
    for (int mt = 0; mt < 2; mt++)
#pragma unroll
        for (int nt = 0; nt < 8; nt++)
#pragma unroll
            for (int q = 0; q < 4; q++) acc[mt][nt][q] = 0.f;

    issue(0, 0);

#pragma unroll 1
    for (int kc = 0; kc < 4; kc++) {
        const int st = kc & 1;
        if (kc < 3) issue(kc + 1, st ^ 1);
        if (kc < 3) cp_async_wait<1>(); else cp_async_wait<0>();
        __syncthreads();

        const uint32_t a_s = s_base + st * STG_SZ + a_lane;
        const uint32_t b_s = s_base + st * STG_SZ + STG_A + b_lane;

#pragma unroll
        for (int ks = 0; ks < 4; ks++) {
            const uint32_t k0b = (uint32_t)(ks * 16) * 2;
            uint32_t bfr[8][2];
#pragma unroll
            for (int ntp = 0; ntp < 4; ntp++) {
                uint32_t r0, r1, r2, r3;
                ldmatrix_x4(r0, r1, r2, r3,
                            b_s + (uint32_t)(ntp * 16 * LDK) * 2 + k0b);
                bfr[2 * ntp][0]     = r0; bfr[2 * ntp][1]     = r1;
                bfr[2 * ntp + 1][0] = r2; bfr[2 * ntp + 1][1] = r3;
            }
#pragma unroll
            for (int mt = 0; mt < 2; mt++) {
                uint32_t a0, a1, a2, a3;
                ldmatrix_x4(a0, a1, a2, a3,
                            a_s + (uint32_t)(mt * 16 * LDK) * 2 + k0b);
#pragma unroll
                for (int nt = 0; nt < 8; nt++)
                    mma_bf16(acc[mt][nt][0], acc[mt][nt][1],
                             acc[mt][nt][2], acc[mt][nt][3],
                             a0, a1, a2, a3, bfr[nt][0], bfr[nt][1]);
            }
        }
        __syncthreads();
    }

    float pos = 0.f, neg = 0.f;
#pragma unroll
    for (int mt = 0; mt < 2; mt++) {
        const int r0 = i0 + mrow + mt * 16 + gid;
#pragma unroll
        for (int nt = 0; nt < 8; nt++) {
            const int c0 = j0 + ncol + nt * 8 + tig * 2;
            float2 alo = __ldg((const float2*)(adj + (size_t)r0 * NDRUGS + c0));
            float2 ahi = __ldg((const float2*)(adj + (size_t)(r0 + 8) * NDRUGS + c0));
            float aa[4] = {alo.x, alo.y, ahi.x, ahi.y};
#pragma unroll
            for (int q = 0; q < 4; q++) {
                float r = acc[mt][nt][q];
                float s = fmaxf(-r, 0.f) + __logf(1.f + __expf(-fabsf(r)));
                if (aa[q] > 0.5f) pos += LOG2F_ - s;
                else              neg += s + r - LOG2F_;
            }
        }
    }

    float* red = (float*)smem;
    __syncthreads();
    red[tid] = pos; red[256 + tid] = neg;
    __syncthreads();
#pragma unroll
    for (int s = 128; s > 0; s >>= 1) {
        if (tid < s) { red[tid] += red[tid + s]; red[256 + tid] += red[256 + tid + s]; }
        __syncthreads();
    }

    // ---- publish partial, detect last block ----
    __shared__ unsigned int isLast;
    if (tid == 0) {
        int bid = blockIdx.y * gridDim.x + blockIdx.x;
        g_partials[bid]        = red[0];
        g_partials[NBLK + bid] = red[256];
        __threadfence();
        unsigned int v = atomicAdd(&g_done, 1u);
        isLast = (v == (unsigned int)(NBLK - 1)) ? 1u : 0u;
    }
    __syncthreads();

    // ---- last block performs the deterministic final reduction ----
    if (isLast) {
        __threadfence();
        double* dsp = (double*)smem;
        double* dsn = dsp + 256;
        double p = 0.0, n = 0.0;
#pragma unroll 4
        for (int i = tid; i < NBLK; i += 256) {
            p += (double)g_partials[i];
            n += (double)g_partials[NBLK + i];
        }
        dsp[tid] = p; dsn[tid] = n;
        __syncthreads();
#pragma unroll
        for (int s = 128; s > 0; s >>= 1) {
            if (tid < s) { dsp[tid] += dsp[tid + s]; dsn[tid] += dsn[tid + s]; }
            __syncthreads();
        }
        if (tid == 0) {
            double E_pos = dsp[0] / (double)NDRUGS;
            double E_neg = dsn[0] / ((double)NDRUGS * (double)(NDRUGS - 1));
            out[0] = (float)(E_neg - E_pos);
            g_done = 0;   // reset for next graph replay
        }
    }
}

// ============================================================================
// launch
// ============================================================================
extern "C" void kernel_launch(void* const* d_in, const int* in_sizes, int n_in,
                              void* d_out, int out_size)
{
    const float* emb  = (const float*)d_in[0];
    const float* feat = (const float*)d_in[1];
    const float* adj  = (const float*)d_in[2];
    const float* g_w1 = (const float*)d_in[4];
    const float* g_b1 = (const float*)d_in[5];
    const float* g_w2 = (const float*)d_in[6];
    const float* g_b2 = (const float*)d_in[7];
    const float* g_w3 = (const float*)d_in[8];
    const float* g_b3 = (const float*)d_in[9];
    const float* g_ws = (const float*)d_in[10];
    const float* g_bs = (const float*)d_in[11];
    const float* l_w1 = (const float*)d_in[12];
    const float* l_b1 = (const float*)d_in[13];
    const float* l_w2 = (const float*)d_in[14];
    const float* l_b2 = (const float*)d_in[15];
    const float* l_w3 = (const float*)d_in[16];
    const float* l_b3 = (const float*)d_in[17];
    const float* l_ws = (const float*)d_in[18];
    const float* l_bs = (const float*)d_in[19];
    float* out = (float*)d_out;

    cudaFuncSetAttribute(score_kernel,
                         cudaFuncAttributeMaxDynamicSharedMemorySize, SM_SIZE);
    cudaFuncSetAttribute(ff_mma_kernel,
                         cudaFuncAttributeMaxDynamicSharedMemorySize, FF_SMEM);

    dim3 tgrid(16, 8);
    wT_kernel<<<tgrid, 256>>>(g_w1, g_w2, g_w3, g_ws, l_w1, l_w2, l_w3, l_ws);

    dim3 fgrid(NDRUGS / 64, 2);
    ff_mma_kernel<<<fgrid, 256, FF_SMEM>>>(emb, feat,
                                           g_b1, g_b2, g_b3, g_bs,
                                           l_b1, l_b2, l_b3, l_bs);

    dim3 grid(NDRUGS / BT, NDRUGS / BT);
    score_kernel<<<grid, 256, SM_SIZE>>>(adj, out);
}

// round 11
// speedup vs baseline: 7.1163x; 1.0414x over previous
#include <cuda_runtime.h>
#include <cuda_bf16.h>
#include <math.h>
#include <stdint.h>

// Problem constants (fixed by the dataset)
#define NDRUGS 8192
#define KDIM   256
#define LOG2F_ 0.69314718055994531f

// ============================ device scratch ================================
__device__ __align__(1024) __nv_bfloat16 g_genc_bf[NDRUGS * KDIM];
__device__ __align__(1024) __nv_bfloat16 g_lenc_bf[NDRUGS * KDIM];
__device__ __align__(1024) __nv_bfloat16 g_wT[8 * KDIM * KDIM];   // bf16 W^T
__device__ __align__(1024) float g_ff_tmp[2 * NDRUGS * KDIM];     // per-encoder shortcut

#define BT   128
#define NBLK ((NDRUGS / BT) * (NDRUGS / BT))   // 64*64 = 4096
__device__ float g_partials[2 * NBLK];
__device__ unsigned int g_done;                // zero-init; self-resetting

// =========================== small PTX helpers ==============================
__device__ __forceinline__ uint32_t smem_u32(const void* p) {
    uint32_t a;
    asm("{ .reg .u64 t; cvta.to.shared.u64 t, %1; cvt.u32.u64 %0, t; }"
        : "=r"(a) : "l"(p));
    return a;
}
__device__ __forceinline__ void cp_async16(uint32_t dst, const void* src) {
    asm volatile("cp.async.cg.shared.global [%0], [%1], 16;"
                 :: "r"(dst), "l"(src) : "memory");
}
__device__ __forceinline__ void cp_async_commit() {
    asm volatile("cp.async.commit_group;" ::: "memory");
}
template <int N>
__device__ __forceinline__ void cp_async_wait() {
    asm volatile("cp.async.wait_group %0;" :: "n"(N) : "memory");
}
__device__ __forceinline__ void prefetch_l2(const void* p) {
    asm volatile("prefetch.global.L2 [%0];" :: "l"(p));
}
__device__ __forceinline__ void ldmatrix_x4(uint32_t& r0, uint32_t& r1,
                                            uint32_t& r2, uint32_t& r3,
                                            uint32_t addr) {
    asm volatile("ldmatrix.sync.aligned.m8n8.x4.shared.b16 {%0,%1,%2,%3}, [%4];"
                 : "=r"(r0), "=r"(r1), "=r"(r2), "=r"(r3) : "r"(addr));
}
__device__ __forceinline__ void mma_bf16(float& d0, float& d1, float& d2, float& d3,
                                         uint32_t a0, uint32_t a1, uint32_t a2,
                                         uint32_t a3, uint32_t b0, uint32_t b1) {
    asm volatile(
        "mma.sync.aligned.m16n8k16.row.col.f32.bf16.bf16.f32 "
        "{%0,%1,%2,%3}, {%4,%5,%6,%7}, {%8,%9}, {%0,%1,%2,%3};"
        : "+f"(d0), "+f"(d1), "+f"(d2), "+f"(d3)
        : "r"(a0), "r"(a1), "r"(a2), "r"(a3), "r"(b0), "r"(b1));
}
__device__ __forceinline__ uint32_t pack_bf2(float a, float b) {
    __nv_bfloat162 h = __floats2bfloat162_rn(a, b);
    return *(uint32_t*)&h;
}

// ============================================================================
// Weight transpose + bf16 convert: g_wT[mat][n*256+k] = bf16(w_mat[k*256+n])
// 64(k) x 32(n) tiles -> grid (32, 8) = 256 blocks, 8 elems/thread each way.
// ============================================================================
__global__ void __launch_bounds__(256)
wT_kernel(const float* __restrict__ m0, const float* __restrict__ m1,
          const float* __restrict__ m2, const float* __restrict__ m3,
          const float* __restrict__ m4, const float* __restrict__ m5,
          const float* __restrict__ m6, const float* __restrict__ m7)
{
    const float* srcs[8] = {m0, m1, m2, m3, m4, m5, m6, m7};
    const float* w = srcs[blockIdx.y];
    __nv_bfloat16* dst = g_wT + (size_t)blockIdx.y * KDIM * KDIM;

    __shared__ float t[64][33];
    const int tid = threadIdx.x;
    const int k0 = (blockIdx.x & 3) * 64;
    const int n0 = (blockIdx.x >> 2) * 32;

#pragma unroll
    for (int i = tid; i < 64 * 32; i += 256) {
        int r = i >> 5, c = i & 31;
        t[r][c] = w[(size_t)(k0 + r) * KDIM + n0 + c];
    }
    __syncthreads();
#pragma unroll
    for (int i = tid; i < 32 * 64; i += 256) {
        int r = i >> 6, c = i & 63;
        dst[(size_t)(n0 + r) * KDIM + k0 + c] = __float2bfloat16(t[c][r]);
    }
}

// ============================================================================
// Fused FF encoder via mma.sync: M=64 rows/CTA, 256 threads (8 warps 32x64),
// 2 CTAs/SM. W streamed as 64-col chunks, single-buffered (4 phases/GEMM).
// SMEM: X0 (64x264 bf16 = 33792) + X1 (33792) + W (256x72 bf16 = 36864)
//     = 104448 B -> 2 CTAs/SM
// ============================================================================
#define FF_LDX  264
#define FF_LDW  72
#define FF_X0   0
#define FF_X1   33792
#define FF_W    67584
#define FF_SMEM 104448

// mode 0: out = A@W + b                   -> tmp (fp32 global)
// mode 1: out = relu(A@W + b)             -> Xdst (bf16 smem)
// mode 2: out = relu(A@W + b) + tmp       -> gout (bf16 global)
__device__ __forceinline__ void ff_gemm(
    char* smem, uint32_t s_base, uint32_t xsrc, uint32_t xdst, int mode,
    const __nv_bfloat16* __restrict__ wmat, const float* __restrict__ bias,
    float* __restrict__ tmp, __nv_bfloat16* __restrict__ gout, int row0,
    int tid, int mrow, int ncol, int gid, int tig,
    uint32_t aL, uint32_t bL)
{
    float acc[2][8][4];
#pragma unroll
    for (int mt = 0; mt < 2; mt++)
#pragma unroll
        for (int nt = 0; nt < 8; nt++)
#pragma unroll
            for (int q = 0; q < 4; q++) acc[mt][nt][q] = 0.f;

    // W chunk: 256 rows x 64 bf16 = 32 KB = 2048 16B-chunks, 8 per thread
    const int wrow = tid >> 3;          // +it*32 -> 0..255
    const int wkq  = (tid & 7) * 8;     // bf16 col 0..56
    auto issueW = [&](int kc) {
        const uint32_t w_s = s_base + FF_W;
#pragma unroll
        for (int it = 0; it < 8; it++) {
            int row = wrow + it * 32;
            cp_async16(w_s + (uint32_t)(row * FF_LDW + wkq) * 2,
                       wmat + (size_t)row * KDIM + kc * 64 + wkq);
        }
        cp_async_commit();
    };

#pragma unroll 1
    for (int kc = 0; kc < 4; kc++) {
        issueW(kc);
        cp_async_wait<0>();
        __syncthreads();

        const uint32_t a_s = s_base + xsrc + aL;
        const uint32_t b_s = s_base + FF_W + bL;
#pragma unroll
        for (int ks = 0; ks < 4; ks++) {
            const uint32_t ak = (uint32_t)((kc * 64 + ks * 16) * 2);
            const uint32_t bk = (uint32_t)(ks * 16 * 2);
            uint32_t bfr[8][2];
#pragma unroll
            for (int ntp = 0; ntp < 4; ntp++) {
                uint32_t r0, r1, r2, r3;
                ldmatrix_x4(r0, r1, r2, r3,
                            b_s + (uint32_t)(ntp * 16 * FF_LDW) * 2 + bk);
                bfr[2 * ntp][0]     = r0; bfr[2 * ntp][1]     = r1;
                bfr[2 * ntp + 1][0] = r2; bfr[2 * ntp + 1][1] = r3;
            }
#pragma unroll
            for (int mt = 0; mt < 2; mt++) {
                uint32_t a0, a1, a2, a3;
                ldmatrix_x4(a0, a1, a2, a3,
                            a_s + (uint32_t)(mt * 16 * FF_LDX) * 2 + ak);
#pragma unroll
                for (int nt = 0; nt < 8; nt++)
                    mma_bf16(acc[mt][nt][0], acc[mt][nt][1],
                             acc[mt][nt][2], acc[mt][nt][3],
                             a0, a1, a2, a3, bfr[nt][0], bfr[nt][1]);
            }
        }
        __syncthreads();
    }

    // ---- epilogue ----
#pragma unroll
    for (int mt = 0; mt < 2; mt++) {
        const int r = mrow + mt * 16 + gid;          // local row < 64
#pragma unroll
        for (int nt = 0; nt < 8; nt++) {
            const int c0 = ncol + nt * 8 + tig * 2;
            float bv0 = __ldg(bias + c0), bv1 = __ldg(bias + c0 + 1);
            float d0 = acc[mt][nt][0] + bv0, d1 = acc[mt][nt][1] + bv1;
            float d2 = acc[mt][nt][2] + bv0, d3 = acc[mt][nt][3] + bv1;
            if (mode == 0) {
                float2 lo = {d0, d1}, hi = {d2, d3};
                *(float2*)(tmp + (size_t)(row0 + r) * KDIM + c0) = lo;
                *(float2*)(tmp + (size_t)(row0 + r + 8) * KDIM + c0) = hi;
            } else if (mode == 1) {
                uint32_t lo = pack_bf2(fmaxf(d0, 0.f), fmaxf(d1, 0.f));
                uint32_t hi = pack_bf2(fmaxf(d2, 0.f), fmaxf(d3, 0.f));
                *(uint32_t*)(smem + xdst + (uint32_t)(r * FF_LDX + c0) * 2) = lo;
                *(uint32_t*)(smem + xdst + (uint32_t)((r + 8) * FF_LDX + c0) * 2) = hi;
            } else {
                float2 t0 = *(const float2*)(tmp + (size_t)(row0 + r) * KDIM + c0);
                float2 t1 = *(const float2*)(tmp + (size_t)(row0 + r + 8) * KDIM + c0);
                uint32_t lo = pack_bf2(fmaxf(d0, 0.f) + t0.x, fmaxf(d1, 0.f) + t0.y);
                uint32_t hi = pack_bf2(fmaxf(d2, 0.f) + t1.x, fmaxf(d3, 0.f) + t1.y);
                *(uint32_t*)(gout + (size_t)(row0 + r) * KDIM + c0) = lo;
                *(uint32_t*)(gout + (size_t)(row0 + r + 8) * KDIM + c0) = hi;
            }
        }
    }
}

__global__ void __launch_bounds__(256, 2)
ff_mma_kernel(const float* __restrict__ xg, const float* __restrict__ xl,
              const float* __restrict__ gb1, const float* __restrict__ gb2,
              const float* __restrict__ gb3, const float* __restrict__ gbs,
              const float* __restrict__ lb1, const float* __restrict__ lb2,
              const float* __restrict__ lb3, const float* __restrict__ lbs)
{
    extern __shared__ char smem[];
    const uint32_t s_base = smem_u32(smem);

    const int tid  = threadIdx.x;
    const int lane = tid & 31;
    const int warp = tid >> 5;
    const int gid  = lane >> 2, tig = lane & 3;
    const int mrow = (warp >> 2) * 32;   // 0..32
    const int ncol = (warp & 3) * 64;    // 0..192

    const int which = blockIdx.y;
    const int row0  = blockIdx.x * 64;

    const float* x  = which ? xl : xg;
    const __nv_bfloat16* wT = g_wT + (size_t)which * 4 * KDIM * KDIM;
    const float* b1 = which ? lb1 : gb1;
    const float* b2 = which ? lb2 : gb2;
    const float* b3 = which ? lb3 : gb3;
    const float* bs = which ? lbs : gbs;
    __nv_bfloat16* gout = which ? g_lenc_bf : g_genc_bf;
    float* tmp = g_ff_tmp + (size_t)which * NDRUGS * KDIM;

    // ---- convert input fp32 -> bf16 into X0 (64x256 = 4096 float4) ----
#pragma unroll
    for (int it = 0; it < 16; it++) {
        int c   = tid + it * 256;
        int row = c >> 6;
        int kq  = (c & 63) * 4;
        float4 v = *(const float4*)(x + (size_t)(row0 + row) * KDIM + kq);
        uint2 u;
        u.x = pack_bf2(v.x, v.y);
        u.y = pack_bf2(v.z, v.w);
        *(uint2*)(smem + FF_X0 + (uint32_t)(row * FF_LDX + kq) * 2) = u;
    }
    __syncthreads();

    const uint32_t aL = (uint32_t)((mrow + (lane & 7) + ((lane >> 3) & 1) * 8)
                                   * FF_LDX + (lane >> 4) * 8) * 2;
    const uint32_t bL = (uint32_t)((ncol + (lane & 7) + (lane >> 4) * 8)
                                   * FF_LDW + ((lane >> 3) & 1) * 8) * 2;

    // shortcut: tmp = X0 @ WsT + bs
    ff_gemm(smem, s_base, FF_X0, 0, 0, wT + 3 * KDIM * KDIM, bs, tmp, gout, row0,
            tid, mrow, ncol, gid, tig, aL, bL);
    // h1 = relu(X0 @ W1T + b1) -> X1
    ff_gemm(smem, s_base, FF_X0, FF_X1, 1, wT + 0 * KDIM * KDIM, b1, tmp, gout, row0,
            tid, mrow, ncol, gid, tig, aL, bL);
    // h2 = relu(X1 @ W2T + b2) -> X0
    ff_gemm(smem, s_base, FF_X1, FF_X0, 1, wT + 1 * KDIM * KDIM, b2, tmp, gout, row0,
            tid, mrow, ncol, gid, tig, aL, bL);
    // out = relu(X0 @ W3T + b3) + tmp -> global bf16
    ff_gemm(smem, s_base, FF_X0, 0, 2, wT + 2 * KDIM * KDIM, b3, tmp, gout, row0,
            tid, mrow, ncol, gid, tig, aL, bL);
}

// ============================================================================
// Score GEMM: mma.sync bf16, 128x128 CTA tile, 4 K-chunks of 64, 2-stage
// cp.async pipeline, ldmatrix, fused JSD epilogue + last-block final reduce.
// ============================================================================
#define LDK     72
#define STG_A   (128 * LDK * 2)
#define STG_SZ  (2 * STG_A)
#define SM_SIZE (2 * STG_SZ)

__global__ void __launch_bounds__(256, 2)
score_kernel(const float* __restrict__ adj, float* __restrict__ out)
{
    extern __shared__ char smem[];
    const uint32_t s_base = smem_u32(smem);

    const int tid  = threadIdx.x;
    const int lane = tid & 31;
    const int warp = tid >> 5;
    const int gid  = lane >> 2;
    const int tig  = lane & 3;
    const int mrow = (warp >> 1) * 32;
    const int ncol = (warp & 1) * 64;

    const int i0 = blockIdx.y * BT;
    const int j0 = blockIdx.x * BT;

#pragma unroll
    for (int t = tid; t < 512; t += 256) {
        int row = t >> 2, seg = t & 3;
        prefetch_l2(adj + (size_t)(i0 + row) * NDRUGS + j0 + seg * 32);
    }

    const int lrow = tid >> 3;
    const int lkq  = (tid & 7) * 8;
    auto issue = [&](int kc, int st) {
        const uint32_t a_s = s_base + st * STG_SZ;
        const uint32_t b_s = a_s + STG_A;
#pragma unroll
        for (int it = 0; it < 4; it++) {
            int row = lrow + it * 32;
            uint32_t soff = (uint32_t)(row * LDK + lkq) * 2;
            const size_t goff = (size_t)row * KDIM + kc * 64 + lkq;
            cp_async16(a_s + soff, g_lenc_bf + (size_t)i0 * KDIM + goff);
            cp_async16(b_s + soff, g_genc_bf + (size_t)j0 * KDIM + goff);
        }
        cp_async_commit();
    };

    const int a_row  = mrow + (lane & 7) + ((lane >> 3) & 1) * 8;
    const int a_koff = (lane >> 4) * 8;
    const uint32_t a_lane = (uint32_t)(a_row * LDK + a_koff) * 2;
    const int b_row  = ncol + (lane & 7) + (lane >> 4) * 8;
    const int b_koff = ((lane >> 3) & 1) * 8;
    const uint32_t b_lane = (uint32_t)(b_row * LDK + b_koff) * 2;

    float acc[2][8][4];
#pragma unroll
    for (int mt = 0; mt < 2; mt++)
#pragma unroll
        for (int nt = 0; nt < 8; nt++)
#pragma unroll
            for (int q = 0; q < 4; q++) acc[mt][nt][q] = 0.f;

    issue(0, 0);

#pragma unroll 1
    for (int kc = 0; kc < 4; kc++) {
        const int st = kc & 1;
        if (kc < 3) issue(kc + 1, st ^ 1);
        if (kc < 3) cp_async_wait<1>(); else cp_async_wait<0>();
        __syncthreads();

        const uint32_t a_s = s_base + st * STG_SZ + a_lane;
        const uint32_t b_s = s_base + st * STG_SZ + STG_A + b_lane;

#pragma unroll
        for (int ks = 0; ks < 4; ks++) {
            const uint32_t k0b = (uint32_t)(ks * 16) * 2;
            uint32_t bfr[8][2];
#pragma unroll
            for (int ntp = 0; ntp < 4; ntp++) {
                uint32_t r0, r1, r2, r3;
                ldmatrix_x4(r0, r1, r2, r3,
                            b_s + (uint32_t)(ntp * 16 * LDK) * 2 + k0b);
                bfr[2 * ntp][0]     = r0; bfr[2 * ntp][1]     = r1;
                bfr[2 * ntp + 1][0] = r2; bfr[2 * ntp + 1][1] = r3;
            }
#pragma unroll
            for (int mt = 0; mt < 2; mt++) {
                uint32_t a0, a1, a2, a3;
                ldmatrix_x4(a0, a1, a2, a3,
                            a_s + (uint32_t)(mt * 16 * LDK) * 2 + k0b);
#pragma unroll
                for (int nt = 0; nt < 8; nt++)
                    mma_bf16(acc[mt][nt][0], acc[mt][nt][1],
                             acc[mt][nt][2], acc[mt][nt][3],
                             a0, a1, a2, a3, bfr[nt][0], bfr[nt][1]);
            }
        }
        __syncthreads();
    }

    float pos = 0.f, neg = 0.f;
#pragma unroll
    for (int mt = 0; mt < 2; mt++) {
        const int r0 = i0 + mrow + mt * 16 + gid;
#pragma unroll
        for (int nt = 0; nt < 8; nt++) {
            const int c0 = j0 + ncol + nt * 8 + tig * 2;
            float2 alo = __ldg((const float2*)(adj + (size_t)r0 * NDRUGS + c0));
            float2 ahi = __ldg((const float2*)(adj + (size_t)(r0 + 8) * NDRUGS + c0));
            float aa[4] = {alo.x, alo.y, ahi.x, ahi.y};
#pragma unroll
            for (int q = 0; q < 4; q++) {
                float r = acc[mt][nt][q];
                float s = fmaxf(-r, 0.f) + __logf(1.f + __expf(-fabsf(r)));
                if (aa[q] > 0.5f) pos += LOG2F_ - s;
                else              neg += s + r - LOG2F_;
            }
        }
    }

    float* red = (float*)smem;
    __syncthreads();
    red[tid] = pos; red[256 + tid] = neg;
    __syncthreads();
#pragma unroll
    for (int s = 128; s > 0; s >>= 1) {
        if (tid < s) { red[tid] += red[tid + s]; red[256 + tid] += red[256 + tid + s]; }
        __syncthreads();
    }

    // ---- publish partial, detect last block ----
    __shared__ unsigned int isLast;
    if (tid == 0) {
        int bid = blockIdx.y * gridDim.x + blockIdx.x;
        g_partials[bid]        = red[0];
        g_partials[NBLK + bid] = red[256];
        __threadfence();
        unsigned int v = atomicAdd(&g_done, 1u);
        isLast = (v == (unsigned int)(NBLK - 1)) ? 1u : 0u;
    }
    __syncthreads();

    // ---- last block performs the deterministic final reduction ----
    if (isLast) {
        __threadfence();
        double* dsp = (double*)smem;
        double* dsn = dsp + 256;
        double p = 0.0, n = 0.0;
#pragma unroll 4
        for (int i = tid; i < NBLK; i += 256) {
            p += (double)g_partials[i];
            n += (double)g_partials[NBLK + i];
        }
        dsp[tid] = p; dsn[tid] = n;
        __syncthreads();
#pragma unroll
        for (int s = 128; s > 0; s >>= 1) {
            if (tid < s) { dsp[tid] += dsp[tid + s]; dsn[tid] += dsn[tid + s]; }
            __syncthreads();
        }
        if (tid == 0) {
            double E_pos = dsp[0] / (double)NDRUGS;
            double E_neg = dsn[0] / ((double)NDRUGS * (double)(NDRUGS - 1));
            out[0] = (float)(E_neg - E_pos);
            g_done = 0;   // reset for next graph replay
        }
    }
}

// ============================================================================
// launch
// ============================================================================
extern "C" void kernel_launch(void* const* d_in, const int* in_sizes, int n_in,
                              void* d_out, int out_size)
{
    const float* emb  = (const float*)d_in[0];
    const float* feat = (const float*)d_in[1];
    const float* adj  = (const float*)d_in[2];
    const float* g_w1 = (const float*)d_in[4];
    const float* g_b1 = (const float*)d_in[5];
    const float* g_w2 = (const float*)d_in[6];
    const float* g_b2 = (const float*)d_in[7];
    const float* g_w3 = (const float*)d_in[8];
    const float* g_b3 = (const float*)d_in[9];
    const float* g_ws = (const float*)d_in[10];
    const float* g_bs = (const float*)d_in[11];
    const float* l_w1 = (const float*)d_in[12];
    const float* l_b1 = (const float*)d_in[13];
    const float* l_w2 = (const float*)d_in[14];
    const float* l_b2 = (const float*)d_in[15];
    const float* l_w3 = (const float*)d_in[16];
    const float* l_b3 = (const float*)d_in[17];
    const float* l_ws = (const float*)d_in[18];
    const float* l_bs = (const float*)d_in[19];
    float* out = (float*)d_out;

    cudaFuncSetAttribute(score_kernel,
                         cudaFuncAttributeMaxDynamicSharedMemorySize, SM_SIZE);
    cudaFuncSetAttribute(ff_mma_kernel,
                         cudaFuncAttributeMaxDynamicSharedMemorySize, FF_SMEM);

    dim3 tgrid(32, 8);
    wT_kernel<<<tgrid, 256>>>(g_w1, g_w2, g_w3, g_ws, l_w1, l_w2, l_w3, l_ws);

    dim3 fgrid(NDRUGS / 64, 2);
    ff_mma_kernel<<<fgrid, 256, FF_SMEM>>>(emb, feat,
                                           g_b1, g_b2, g_b3, g_bs,
                                           l_b1, l_b2, l_b3, l_bs);

    dim3 grid(NDRUGS / BT, NDRUGS / BT);
    score_kernel<<<grid, 256, SM_SIZE>>>(adj, out);
}

// round 12
// speedup vs baseline: 7.1385x; 1.0031x over previous
#include <cuda_runtime.h>
#include <cuda_bf16.h>
#include <math.h>
#include <stdint.h>

// Problem constants (fixed by the dataset)
#define NDRUGS 8192
#define KDIM   256
#define LOG2F_ 0.69314718055994531f

// ============================ device scratch ================================
__device__ __align__(1024) __nv_bfloat16 g_genc_bf[NDRUGS * KDIM];
__device__ __align__(1024) __nv_bfloat16 g_lenc_bf[NDRUGS * KDIM];
__device__ __align__(1024) __nv_bfloat16 g_wT[8 * KDIM * KDIM];   // bf16 W^T
__device__ __align__(1024) float g_ff_tmp[2 * NDRUGS * KDIM];     // per-encoder shortcut

#define BT   128
#define NBLK ((NDRUGS / BT) * (NDRUGS / BT))   // 64*64 = 4096
__device__ float g_partials[2 * NBLK];
__device__ unsigned int g_done;                // zero-init; self-resetting

// =========================== small PTX helpers ==============================
__device__ __forceinline__ uint32_t smem_u32(const void* p) {
    uint32_t a;
    asm("{ .reg .u64 t; cvta.to.shared.u64 t, %1; cvt.u32.u64 %0, t; }"
        : "=r"(a) : "l"(p));
    return a;
}
__device__ __forceinline__ void cp_async16(uint32_t dst, const void* src) {
    asm volatile("cp.async.cg.shared.global [%0], [%1], 16;"
                 :: "r"(dst), "l"(src) : "memory");
}
__device__ __forceinline__ void cp_async_commit() {
    asm volatile("cp.async.commit_group;" ::: "memory");
}
template <int N>
__device__ __forceinline__ void cp_async_wait() {
    asm volatile("cp.async.wait_group %0;" :: "n"(N) : "memory");
}
__device__ __forceinline__ void prefetch_l2(const void* p) {
    asm volatile("prefetch.global.L2 [%0];" :: "l"(p));
}
__device__ __forceinline__ void ldmatrix_x4(uint32_t& r0, uint32_t& r1,
                                            uint32_t& r2, uint32_t& r3,
                                            uint32_t addr) {
    asm volatile("ldmatrix.sync.aligned.m8n8.x4.shared.b16 {%0,%1,%2,%3}, [%4];"
                 : "=r"(r0), "=r"(r1), "=r"(r2), "=r"(r3) : "r"(addr));
}
__device__ __forceinline__ void mma_bf16(float& d0, float& d1, float& d2, float& d3,
                                         uint32_t a0, uint32_t a1, uint32_t a2,
                                         uint32_t a3, uint32_t b0, uint32_t b1) {
    asm volatile(
        "mma.sync.aligned.m16n8k16.row.col.f32.bf16.bf16.f32 "
        "{%0,%1,%2,%3}, {%4,%5,%6,%7}, {%8,%9}, {%0,%1,%2,%3};"
        : "+f"(d0), "+f"(d1), "+f"(d2), "+f"(d3)
        : "r"(a0), "r"(a1), "r"(a2), "r"(a3), "r"(b0), "r"(b1));
}
__device__ __forceinline__ uint32_t pack_bf2(float a, float b) {
    __nv_bfloat162 h = __floats2bfloat162_rn(a, b);
    return *(uint32_t*)&h;
}

// ============================================================================
// Weight transpose + bf16 convert: g_wT[mat][n*256+k] = bf16(w_mat[k*256+n])
// 32x32 tiles -> grid (64, 8) = 512 blocks, 256 threads, 4 elems/thread.
// ============================================================================
__global__ void __launch_bounds__(256)
wT_kernel(const float* __restrict__ m0, const float* __restrict__ m1,
          const float* __restrict__ m2, const float* __restrict__ m3,
          const float* __restrict__ m4, const float* __restrict__ m5,
          const float* __restrict__ m6, const float* __restrict__ m7)
{
    const float* srcs[8] = {m0, m1, m2, m3, m4, m5, m6, m7};
    const float* w = srcs[blockIdx.y];
    __nv_bfloat16* dst = g_wT + (size_t)blockIdx.y * KDIM * KDIM;

    __shared__ float t[32][33];
    const int tid = threadIdx.x;
    const int k0 = (blockIdx.x & 7) * 32;
    const int n0 = (blockIdx.x >> 3) * 32;

#pragma unroll
    for (int i = tid; i < 32 * 32; i += 256) {
        int r = i >> 5, c = i & 31;
        t[r][c] = w[(size_t)(k0 + r) * KDIM + n0 + c];
    }
    __syncthreads();
#pragma unroll
    for (int i = tid; i < 32 * 32; i += 256) {
        int r = i >> 5, c = i & 31;
        dst[(size_t)(n0 + r) * KDIM + k0 + c] = __float2bfloat16(t[c][r]);
    }
}

// ============================================================================
// Fused FF encoder via mma.sync: M=64 rows/CTA, 256 threads (8 warps 32x64),
// 2 CTAs/SM. Single X buffer (in-place update), W 64-col chunks double-buffered.
// SMEM: X (64x264 bf16 = 33792) + W 2x(256x72 bf16 = 36864) = 107520 B
// ============================================================================
#define FF_LDX  264
#define FF_LDW  72
#define FF_X    0
#define FF_W    33792
#define FF_WSTG 36864
#define FF_SMEM 107520

// mode 0: out = A@W + b                   -> tmp (fp32 global)
// mode 1: out = relu(A@W + b)             -> X (bf16 smem, in place)
// mode 2: out = relu(A@W + b) + tmp       -> gout (bf16 global)
__device__ __forceinline__ void ff_gemm(
    char* smem, uint32_t s_base, int mode,
    const __nv_bfloat16* __restrict__ wmat, const float* __restrict__ bias,
    float* __restrict__ tmp, __nv_bfloat16* __restrict__ gout, int row0,
    int tid, int mrow, int ncol, int gid, int tig,
    uint32_t aL, uint32_t bL)
{
    float acc[2][8][4];
#pragma unroll
    for (int mt = 0; mt < 2; mt++)
#pragma unroll
        for (int nt = 0; nt < 8; nt++)
#pragma unroll
            for (int q = 0; q < 4; q++) acc[mt][nt][q] = 0.f;

    // W chunk: 256 rows x 64 bf16 = 32 KB = 2048 16B-chunks, 8 per thread
    const int wrow = tid >> 3;          // +it*32 -> 0..255
    const int wkq  = (tid & 7) * 8;     // bf16 col 0..56
    auto issueW = [&](int kc, int st) {
        const uint32_t w_s = s_base + FF_W + st * FF_WSTG;
#pragma unroll
        for (int it = 0; it < 8; it++) {
            int row = wrow + it * 32;
            cp_async16(w_s + (uint32_t)(row * FF_LDW + wkq) * 2,
                       wmat + (size_t)row * KDIM + kc * 64 + wkq);
        }
        cp_async_commit();
    };

    issueW(0, 0);
#pragma unroll 1
    for (int kc = 0; kc < 4; kc++) {
        const int st = kc & 1;
        if (kc < 3) issueW(kc + 1, st ^ 1);
        if (kc < 3) cp_async_wait<1>(); else cp_async_wait<0>();
        __syncthreads();

        const uint32_t a_s = s_base + FF_X + aL;
        const uint32_t b_s = s_base + FF_W + st * FF_WSTG + bL;
#pragma unroll
        for (int ks = 0; ks < 4; ks++) {
            const uint32_t ak = (uint32_t)((kc * 64 + ks * 16) * 2);
            const uint32_t bk = (uint32_t)(ks * 16 * 2);
            uint32_t bfr[8][2];
#pragma unroll
            for (int ntp = 0; ntp < 4; ntp++) {
                uint32_t r0, r1, r2, r3;
                ldmatrix_x4(r0, r1, r2, r3,
                            b_s + (uint32_t)(ntp * 16 * FF_LDW) * 2 + bk);
                bfr[2 * ntp][0]     = r0; bfr[2 * ntp][1]     = r1;
                bfr[2 * ntp + 1][0] = r2; bfr[2 * ntp + 1][1] = r3;
            }
#pragma unroll
            for (int mt = 0; mt < 2; mt++) {
                uint32_t a0, a1, a2, a3;
                ldmatrix_x4(a0, a1, a2, a3,
                            a_s + (uint32_t)(mt * 16 * FF_LDX) * 2 + ak);
#pragma unroll
                for (int nt = 0; nt < 8; nt++)
                    mma_bf16(acc[mt][nt][0], acc[mt][nt][1],
                             acc[mt][nt][2], acc[mt][nt][3],
                             a0, a1, a2, a3, bfr[nt][0], bfr[nt][1]);
            }
        }
        __syncthreads();
    }
    // after the last barrier above, no thread reads X again -> in-place OK

    // ---- epilogue ----
#pragma unroll
    for (int mt = 0; mt < 2; mt++) {
        const int r = mrow + mt * 16 + gid;          // local row < 64
#pragma unroll
        for (int nt = 0; nt < 8; nt++) {
            const int c0 = ncol + nt * 8 + tig * 2;
            float bv0 = __ldg(bias + c0), bv1 = __ldg(bias + c0 + 1);
            float d0 = acc[mt][nt][0] + bv0, d1 = acc[mt][nt][1] + bv1;
            float d2 = acc[mt][nt][2] + bv0, d3 = acc[mt][nt][3] + bv1;
            if (mode == 0) {
                float2 lo = {d0, d1}, hi = {d2, d3};
                *(float2*)(tmp + (size_t)(row0 + r) * KDIM + c0) = lo;
                *(float2*)(tmp + (size_t)(row0 + r + 8) * KDIM + c0) = hi;
            } else if (mode == 1) {
                uint32_t lo = pack_bf2(fmaxf(d0, 0.f), fmaxf(d1, 0.f));
                uint32_t hi = pack_bf2(fmaxf(d2, 0.f), fmaxf(d3, 0.f));
                *(uint32_t*)(smem + FF_X + (uint32_t)(r * FF_LDX + c0) * 2) = lo;
                *(uint32_t*)(smem + FF_X + (uint32_t)((r + 8) * FF_LDX + c0) * 2) = hi;
            } else {
                float2 t0 = *(const float2*)(tmp + (size_t)(row0 + r) * KDIM + c0);
                float2 t1 = *(const float2*)(tmp + (size_t)(row0 + r + 8) * KDIM + c0);
                uint32_t lo = pack_bf2(fmaxf(d0, 0.f) + t0.x, fmaxf(d1, 0.f) + t0.y);
                uint32_t hi = pack_bf2(fmaxf(d2, 0.f) + t1.x, fmaxf(d3, 0.f) + t1.y);
                *(uint32_t*)(gout + (size_t)(row0 + r) * KDIM + c0) = lo;
                *(uint32_t*)(gout + (size_t)(row0 + r + 8) * KDIM + c0) = hi;
            }
        }
    }
    __syncthreads();   // epilogue writes visible before next GEMM reads X
}

__global__ void __launch_bounds__(256, 2)
ff_mma_kernel(const float* __restrict__ xg, const float* __restrict__ xl,
              const float* __restrict__ gb1, const float* __restrict__ gb2,
              const float* __restrict__ gb3, const float* __restrict__ gbs,
              const float* __restrict__ lb1, const float* __restrict__ lb2,
              const float* __restrict__ lb3, const float* __restrict__ lbs)
{
    extern __shared__ char smem[];
    const uint32_t s_base = smem_u32(smem);

    const int tid  = threadIdx.x;
    const int lane = tid & 31;
    const int warp = tid >> 5;
    const int gid  = lane >> 2, tig = lane & 3;
    const int mrow = (warp >> 2) * 32;   // 0..32
    const int ncol = (warp & 3) * 64;    // 0..192

    const int which = blockIdx.y;
    const int row0  = blockIdx.x * 64;

    const float* x  = which ? xl : xg;
    const __nv_bfloat16* wT = g_wT + (size_t)which * 4 * KDIM * KDIM;
    const float* b1 = which ? lb1 : gb1;
    const float* b2 = which ? lb2 : gb2;
    const float* b3 = which ? lb3 : gb3;
    const float* bs = which ? lbs : gbs;
    __nv_bfloat16* gout = which ? g_lenc_bf : g_genc_bf;
    float* tmp = g_ff_tmp + (size_t)which * NDRUGS * KDIM;

    // ---- convert input fp32 -> bf16 into X (64x256 = 4096 float4) ----
#pragma unroll
    for (int it = 0; it < 16; it++) {
        int c   = tid + it * 256;
        int row = c >> 6;
        int kq  = (c & 63) * 4;
        float4 v = *(const float4*)(x + (size_t)(row0 + row) * KDIM + kq);
        uint2 u;
        u.x = pack_bf2(v.x, v.y);
        u.y = pack_bf2(v.z, v.w);
        *(uint2*)(smem + FF_X + (uint32_t)(row * FF_LDX + kq) * 2) = u;
    }
    __syncthreads();

    const uint32_t aL = (uint32_t)((mrow + (lane & 7) + ((lane >> 3) & 1) * 8)
                                   * FF_LDX + (lane >> 4) * 8) * 2;
    const uint32_t bL = (uint32_t)((ncol + (lane & 7) + (lane >> 4) * 8)
                                   * FF_LDW + ((lane >> 3) & 1) * 8) * 2;

    // shortcut: tmp = X @ WsT + bs   (X unchanged)
    ff_gemm(smem, s_base, 0, wT + 3 * KDIM * KDIM, bs, tmp, gout, row0,
            tid, mrow, ncol, gid, tig, aL, bL);
    // h1 = relu(X @ W1T + b1) -> X
    ff_gemm(smem, s_base, 1, wT + 0 * KDIM * KDIM, b1, tmp, gout, row0,
            tid, mrow, ncol, gid, tig, aL, bL);
    // h2 = relu(X @ W2T + b2) -> X
    ff_gemm(smem, s_base, 1, wT + 1 * KDIM * KDIM, b2, tmp, gout, row0,
            tid, mrow, ncol, gid, tig, aL, bL);
    // out = relu(X @ W3T + b3) + tmp -> global bf16
    ff_gemm(smem, s_base, 2, wT + 2 * KDIM * KDIM, b3, tmp, gout, row0,
            tid, mrow, ncol, gid, tig, aL, bL);
}

// ============================================================================
// Score GEMM: mma.sync bf16, 128x128 CTA tile, 4 K-chunks of 64, 2-stage
// cp.async pipeline, ldmatrix, fused JSD epilogue + last-block final reduce.
// ============================================================================
#define LDK     72
#define STG_A   (128 * LDK * 2)
#define STG_SZ  (2 * STG_A)
#define SM_SIZE (2 * STG_SZ)

__global__ void __launch_bounds__(256, 2)
score_kernel(const float* __restrict__ adj, float* __restrict__ out)
{
    extern __shared__ char smem[];
    const uint32_t s_base = smem_u32(smem);

    const int tid  = threadIdx.x;
    const int lane = tid & 31;
    const int warp = tid >> 5;
    const int gid  = lane >> 2;
    const int tig  = lane & 3;
    const int mrow = (warp >> 1) * 32;
    const int ncol = (warp & 1) * 64;

    const int i0 = blockIdx.y * BT;
    const int j0 = blockIdx.x * BT;

#pragma unroll
    for (int t = tid; t < 512; t += 256) {
        int row = t >> 2, seg = t & 3;
        prefetch_l2(adj + (size_t)(i0 + row) * NDRUGS + j0 + seg * 32);
    }

    const int lrow = tid >> 3;
    const int lkq  = (tid & 7) * 8;
    auto issue = [&](int kc, int st) {
        const uint32_t a_s = s_base + st * STG_SZ;
        const uint32_t b_s = a_s + STG_A;
#pragma unroll
        for (int it = 0; it < 4; it++) {
            int row = lrow + it * 32;
            uint32_t soff = (uint32_t)(row * LDK + lkq) * 2;
            const size_t goff = (size_t)row * KDIM + kc * 64 + lkq;
            cp_async16(a_s + soff, g_lenc_bf + (size_t)i0 * KDIM + goff);
            cp_async16(b_s + soff, g_genc_bf + (size_t)j0 * KDIM + goff);
        }
        cp_async_commit();
    };

    const int a_row  = mrow + (lane & 7) + ((lane >> 3) & 1) * 8;
    const int a_koff = (lane >> 4) * 8;
    const uint32_t a_lane = (uint32_t)(a_row * LDK + a_koff) * 2;
    const int b_row  = ncol + (lane & 7) + (lane >> 4) * 8;
    const int b_koff = ((lane >> 3) & 1) * 8;
    const uint32_t b_lane = (uint32_t)(b_row * LDK + b_koff) * 2;

    float acc[2][8][4];
#pragma unroll
    for (int mt = 0; mt < 2; mt++)
#pragma unroll
        for (int nt = 0; nt < 8; nt++)
#pragma unroll
            for (int q = 0; q < 4; q++) acc[mt][nt][q] = 0.f;

    issue(0, 0);

#pragma unroll 1
    for (int kc = 0; kc < 4; kc++) {
        const int st = kc & 1;
        if (kc < 3) issue(kc + 1, st ^ 1);
        if (kc < 3) cp_async_wait<1>(); else cp_async_wait<0>();
        __syncthreads();

        const uint32_t a_s = s_base + st * STG_SZ + a_lane;
        const uint32_t b_s = s_base + st * STG_SZ + STG_A + b_lane;

#pragma unroll
        for (int ks = 0; ks < 4; ks++) {
            const uint32_t k0b = (uint32_t)(ks * 16) * 2;
            uint32_t bfr[8][2];
#pragma unroll
            for (int ntp = 0; ntp < 4; ntp++) {
                uint32_t r0, r1, r2, r3;
                ldmatrix_x4(r0, r1, r2, r3,
                            b_s + (uint32_t)(ntp * 16 * LDK) * 2 + k0b);
                bfr[2 * ntp][0]     = r0; bfr[2 * ntp][1]     = r1;
                bfr[2 * ntp + 1][0] = r2; bfr[2 * ntp + 1][1] = r3;
            }
#pragma unroll
            for (int mt = 0; mt < 2; mt++) {
                uint32_t a0, a1, a2, a3;
                ldmatrix_x4(a0, a1, a2, a3,
                            a_s + (uint32_t)(mt * 16 * LDK) * 2 + k0b);
#pragma unroll
                for (int nt = 0; nt < 8; nt++)
                    mma_bf16(acc[mt][nt][0], acc[mt][nt][1],
                             acc[mt][nt][2], acc[mt][nt][3],
                             a0, a1, a2, a3, bfr[nt][0], bfr[nt][1]);
            }
        }
        __syncthreads();
    }

    float pos = 0.f, neg = 0.f;
#pragma unroll
    for (int mt = 0; mt < 2; mt++) {
        const int r0 = i0 + mrow + mt * 16 + gid;
#pragma unroll
        for (int nt = 0; nt < 8; nt++) {
            const int c0 = j0 + ncol + nt * 8 + tig * 2;
            float2 alo = __ldg((const float2*)(adj + (size_t)r0 * NDRUGS + c0));
            float2 ahi = __ldg((const float2*)(adj + (size_t)(r0 + 8) * NDRUGS + c0));
            float aa[4] = {alo.x, alo.y, ahi.x, ahi.y};
#pragma unroll
            for (int q = 0; q < 4; q++) {
                float r = acc[mt][nt][q];
                float s = fmaxf(-r, 0.f) + __logf(1.f + __expf(-fabsf(r)));
                if (aa[q] > 0.5f) pos += LOG2F_ - s;
                else              neg += s + r - LOG2F_;
            }
        }
    }

    float* red = (float*)smem;
    __syncthreads();
    red[tid] = pos; red[256 + tid] = neg;
    __syncthreads();
#pragma unroll
    for (int s = 128; s > 0; s >>= 1) {
        if (tid < s) { red[tid] += red[tid + s]; red[256 + tid] += red[256 + tid + s]; }
        __syncthreads();
    }

    // ---- publish partial, detect last block ----
    __shared__ unsigned int isLast;
    if (tid == 0) {
        int bid = blockIdx.y * gridDim.x + blockIdx.x;
        g_partials[bid]        = red[0];
        g_partials[NBLK + bid] = red[256];
        __threadfence();
        unsigned int v = atomicAdd(&g_done, 1u);
        isLast = (v == (unsigned int)(NBLK - 1)) ? 1u : 0u;
    }
    __syncthreads();

    // ---- last block performs the deterministic final reduction ----
    if (isLast) {
        __threadfence();
        double* dsp = (double*)smem;
        double* dsn = dsp + 256;
        double p = 0.0, n = 0.0;
#pragma unroll 4
        for (int i = tid; i < NBLK; i += 256) {
            p += (double)g_partials[i];
            n += (double)g_partials[NBLK + i];
        }
        dsp[tid] = p; dsn[tid] = n;
        __syncthreads();
#pragma unroll
        for (int s = 128; s > 0; s >>= 1) {
            if (tid < s) { dsp[tid] += dsp[tid + s]; dsn[tid] += dsn[tid + s]; }
            __syncthreads();
        }
        if (tid == 0) {
            double E_pos = dsp[0] / (double)NDRUGS;
            double E_neg = dsn[0] / ((double)NDRUGS * (double)(NDRUGS - 1));
            out[0] = (float)(E_neg - E_pos);
            g_done = 0;   // reset for next graph replay
        }
    }
}

// ============================================================================
// launch
// ============================================================================
extern "C" void kernel_launch(void* const* d_in, const int* in_sizes, int n_in,
                              void* d_out, int out_size)
{
    const float* emb  = (const float*)d_in[0];
    const float* feat = (const float*)d_in[1];
    const float* adj  = (const float*)d_in[2];
    const float* g_w1 = (const float*)d_in[4];
    const float* g_b1 = (const float*)d_in[5];
    const float* g_w2 = (const float*)d_in[6];
    const float* g_b2 = (const float*)d_in[7];
    const float* g_w3 = (const float*)d_in[8];
    const float* g_b3 = (const float*)d_in[9];
    const float* g_ws = (const float*)d_in[10];
    const float* g_bs = (const float*)d_in[11];
    const float* l_w1 = (const float*)d_in[12];
    const float* l_b1 = (const float*)d_in[13];
    const float* l_w2 = (const float*)d_in[14];
    const float* l_b2 = (const float*)d_in[15];
    const float* l_w3 = (const float*)d_in[16];
    const float* l_b3 = (const float*)d_in[17];
    const float* l_ws = (const float*)d_in[18];
    const float* l_bs = (const float*)d_in[19];
    float* out = (float*)d_out;

    cudaFuncSetAttribute(score_kernel,
                         cudaFuncAttributeMaxDynamicSharedMemorySize, SM_SIZE);
    cudaFuncSetAttribute(ff_mma_kernel,
                         cudaFuncAttributeMaxDynamicSharedMemorySize, FF_SMEM);

    dim3 tgrid(64, 8);
    wT_kernel<<<tgrid, 256>>>(g_w1, g_w2, g_w3, g_ws, l_w1, l_w2, l_w3, l_ws);

    dim3 fgrid(NDRUGS / 64, 2);
    ff_mma_kernel<<<fgrid, 256, FF_SMEM>>>(emb, feat,
                                           g_b1, g_b2, g_b3, g_bs,
                                           l_b1, l_b2, l_b3, l_bs);

    dim3 grid(NDRUGS / BT, NDRUGS / BT);
    score_kernel<<<grid, 256, SM_SIZE>>>(adj, out);
}

// round 15
// speedup vs baseline: 7.2610x; 1.0172x over previous
#include <cuda_runtime.h>
#include <cuda_bf16.h>
#include <math.h>
#include <stdint.h>

// Problem constants (fixed by the dataset)
#define NDRUGS 8192
#define KDIM   256
#define LOG2F_ 0.69314718055994531f

// ============================ device scratch ================================
__device__ __align__(1024) __nv_bfloat16 g_genc_bf[NDRUGS * KDIM];
__device__ __align__(1024) __nv_bfloat16 g_lenc_bf[NDRUGS * KDIM];
__device__ __align__(1024) __nv_bfloat16 g_wT[8 * KDIM * KDIM];   // bf16 W^T

#define BT   128
#define NBLK ((NDRUGS / BT) * (NDRUGS / BT))   // 64*64 = 4096
__device__ float g_partials[2 * NBLK];
__device__ unsigned int g_done;                // zero-init; self-resetting

// =========================== small PTX helpers ==============================
__device__ __forceinline__ uint32_t smem_u32(const void* p) {
    uint32_t a;
    asm("{ .reg .u64 t; cvta.to.shared.u64 t, %1; cvt.u32.u64 %0, t; }"
        : "=r"(a) : "l"(p));
    return a;
}
__device__ __forceinline__ void cp_async16(uint32_t dst, const void* src) {
    asm volatile("cp.async.cg.shared.global [%0], [%1], 16;"
                 :: "r"(dst), "l"(src) : "memory");
}
__device__ __forceinline__ void cp_async_commit() {
    asm volatile("cp.async.commit_group;" ::: "memory");
}
template <int N>
__device__ __forceinline__ void cp_async_wait() {
    asm volatile("cp.async.wait_group %0;" :: "n"(N) : "memory");
}
__device__ __forceinline__ void prefetch_l2(const void* p) {
    asm volatile("prefetch.global.L2 [%0];" :: "l"(p));
}
__device__ __forceinline__ void ldmatrix_x4(uint32_t& r0, uint32_t& r1,
                                            uint32_t& r2, uint32_t& r3,
                                            uint32_t addr) {
    asm volatile("ldmatrix.sync.aligned.m8n8.x4.shared.b16 {%0,%1,%2,%3}, [%4];"
                 : "=r"(r0), "=r"(r1), "=r"(r2), "=r"(r3) : "r"(addr));
}
__device__ __forceinline__ void mma_bf16(float& d0, float& d1, float& d2, float& d3,
                                         uint32_t a0, uint32_t a1, uint32_t a2,
                                         uint32_t a3, uint32_t b0, uint32_t b1) {
    asm volatile(
        "mma.sync.aligned.m16n8k16.row.col.f32.bf16.bf16.f32 "
        "{%0,%1,%2,%3}, {%4,%5,%6,%7}, {%8,%9}, {%0,%1,%2,%3};"
        : "+f"(d0), "+f"(d1), "+f"(d2), "+f"(d3)
        : "r"(a0), "r"(a1), "r"(a2), "r"(a3), "r"(b0), "r"(b1));
}
__device__ __forceinline__ uint32_t pack_bf2(float a, float b) {
    __nv_bfloat162 h = __floats2bfloat162_rn(a, b);
    return *(uint32_t*)&h;
}

// ============================================================================
// Weight transpose + bf16 convert: g_wT[mat][n*256+k] = bf16(w_mat[k*256+n])
// 32x32 tiles -> grid (64, 8) = 512 blocks.
// ============================================================================
__global__ void __launch_bounds__(256)
wT_kernel(const float* __restrict__ m0, const float* __restrict__ m1,
          const float* __restrict__ m2, const float* __restrict__ m3,
          const float* __restrict__ m4, const float* __restrict__ m5,
          const float* __restrict__ m6, const float* __restrict__ m7)
{
    const float* srcs[8] = {m0, m1, m2, m3, m4, m5, m6, m7};
    const float* w = srcs[blockIdx.y];
    __nv_bfloat16* dst = g_wT + (size_t)blockIdx.y * KDIM * KDIM;

    __shared__ float t[32][33];
    const int tid = threadIdx.x;
    const int k0 = (blockIdx.x & 7) * 32;
    const int n0 = (blockIdx.x >> 3) * 32;

#pragma unroll
    for (int i = tid; i < 32 * 32; i += 256) {
        int r = i >> 5, c = i & 31;
        t[r][c] = w[(size_t)(k0 + r) * KDIM + n0 + c];
    }
    __syncthreads();
#pragma unroll
    for (int i = tid; i < 32 * 32; i += 256) {
        int r = i >> 5, c = i & 31;
        dst[(size_t)(n0 + r) * KDIM + k0 + c] = __float2bfloat16(t[c][r]);
    }
}

// ============================================================================
// Fused FF encoder via mma.sync: M=64 rows/CTA, 256 threads (8 warps 32x64),
// 2 CTAs/SM. Shortcut kept in SMEM (bf16). W single-buffered 64-col chunks.
// SMEM: X (64x264 bf16 = 33792) + TMP (same) + W (256x72 bf16 = 36864)
//     = 104448 B -> 2 CTAs/SM
// ============================================================================
#define FF_LDX  264
#define FF_LDW  72
#define FF_X    0
#define FF_TMP  33792
#define FF_W    67584
#define FF_SMEM 104448

// mode 0: out = A@W + b                       -> TMP (bf16 smem)
// mode 1: out = relu(A@W + b)                 -> X (bf16 smem, in place)
// mode 2: out = relu(A@W + b) + TMP           -> gout (bf16 global)
__device__ __forceinline__ void ff_gemm(
    char* smem, uint32_t s_base, int mode,
    const __nv_bfloat16* __restrict__ wmat, const float* __restrict__ bias,
    __nv_bfloat16* __restrict__ gout, int row0,
    int tid, int mrow, int ncol, int gid, int tig,
    uint32_t aL, uint32_t bL)
{
    float acc[2][8][4];
#pragma unroll
    for (int mt = 0; mt < 2; mt++)
#pragma unroll
        for (int nt = 0; nt < 8; nt++)
#pragma unroll
            for (int q = 0; q < 4; q++) acc[mt][nt][q] = 0.f;

    // W chunk: 256 rows x 64 bf16 = 32 KB = 2048 16B-chunks, 8 per thread
    const int wrow = tid >> 3;          // +it*32 -> 0..255
    const int wkq  = (tid & 7) * 8;     // bf16 col 0..56
    auto issueW = [&](int kc) {
        const uint32_t w_s = s_base + FF_W;
#pragma unroll
        for (int it = 0; it < 8; it++) {
            int row = wrow + it * 32;
            cp_async16(w_s + (uint32_t)(row * FF_LDW + wkq) * 2,
                       wmat + (size_t)row * KDIM + kc * 64 + wkq);
        }
        cp_async_commit();
    };

#pragma unroll 1
    for (int kc = 0; kc < 4; kc++) {
        issueW(kc);
        cp_async_wait<0>();
        __syncthreads();

        const uint32_t a_s = s_base + FF_X + aL;
        const uint32_t b_s = s_base + FF_W + bL;
#pragma unroll
        for (int ks = 0; ks < 4; ks++) {
            const uint32_t ak = (uint32_t)((kc * 64 + ks * 16) * 2);
            const uint32_t bk = (uint32_t)(ks * 16 * 2);
            uint32_t bfr[8][2];
#pragma unroll
            for (int ntp = 0; ntp < 4; ntp++) {
                uint32_t r0, r1, r2, r3;
                ldmatrix_x4(r0, r1, r2, r3,
                            b_s + (uint32_t)(ntp * 16 * FF_LDW) * 2 + bk);
                bfr[2 * ntp][0]     = r0; bfr[2 * ntp][1]     = r1;
                bfr[2 * ntp + 1][0] = r2; bfr[2 * ntp + 1][1] = r3;
            }
#pragma unroll
            for (int mt = 0; mt < 2; mt++) {
                uint32_t a0, a1, a2, a3;
                ldmatrix_x4(a0, a1, a2, a3,
                            a_s + (uint32_t)(mt * 16 * FF_LDX) * 2 + ak);
#pragma unroll
                for (int nt = 0; nt < 8; nt++)
                    mma_bf16(acc[mt][nt][0], acc[mt][nt][1],
                             acc[mt][nt][2], acc[mt][nt][3],
                             a0, a1, a2, a3, bfr[nt][0], bfr[nt][1]);
            }
        }
        __syncthreads();
    }
    // after the last barrier above, no thread reads X again -> in-place OK

    // ---- epilogue ----
#pragma unroll
    for (int mt = 0; mt < 2; mt++) {
        const int r = mrow + mt * 16 + gid;          // local row < 64
#pragma unroll
        for (int nt = 0; nt < 8; nt++) {
            const int c0 = ncol + nt * 8 + tig * 2;
            float bv0 = __ldg(bias + c0), bv1 = __ldg(bias + c0 + 1);
            float d0 = acc[mt][nt][0] + bv0, d1 = acc[mt][nt][1] + bv1;
            float d2 = acc[mt][nt][2] + bv0, d3 = acc[mt][nt][3] + bv1;
            const uint32_t off_lo = (uint32_t)(r * FF_LDX + c0) * 2;
            const uint32_t off_hi = (uint32_t)((r + 8) * FF_LDX + c0) * 2;
            if (mode == 0) {
                *(uint32_t*)(smem + FF_TMP + off_lo) = pack_bf2(d0, d1);
                *(uint32_t*)(smem + FF_TMP + off_hi) = pack_bf2(d2, d3);
            } else if (mode == 1) {
                *(uint32_t*)(smem + FF_X + off_lo) =
                    pack_bf2(fmaxf(d0, 0.f), fmaxf(d1, 0.f));
                *(uint32_t*)(smem + FF_X + off_hi) =
                    pack_bf2(fmaxf(d2, 0.f), fmaxf(d3, 0.f));
            } else {
                uint32_t ulo = *(const uint32_t*)(smem + FF_TMP + off_lo);
                uint32_t uhi = *(const uint32_t*)(smem + FF_TMP + off_hi);
                float2 t0 = __bfloat1622float2(*(__nv_bfloat162*)&ulo);
                float2 t1 = __bfloat1622float2(*(__nv_bfloat162*)&uhi);
                *(uint32_t*)(gout + (size_t)(row0 + r) * KDIM + c0) =
                    pack_bf2(fmaxf(d0, 0.f) + t0.x, fmaxf(d1, 0.f) + t0.y);
                *(uint32_t*)(gout + (size_t)(row0 + r + 8) * KDIM + c0) =
                    pack_bf2(fmaxf(d2, 0.f) + t1.x, fmaxf(d3, 0.f) + t1.y);
            }
        }
    }
    __syncthreads();   // epilogue writes visible before next GEMM reads X
}

__global__ void __launch_bounds__(256, 2)
ff_mma_kernel(const float* __restrict__ xg, const float* __restrict__ xl,
              const float* __restrict__ gb1, const float* __restrict__ gb2,
              const float* __restrict__ gb3, const float* __restrict__ gbs,
              const float* __restrict__ lb1, const float* __restrict__ lb2,
              const float* __restrict__ lb3, const float* __restrict__ lbs)
{
    extern __shared__ char smem[];
    const uint32_t s_base = smem_u32(smem);

    const int tid  = threadIdx.x;
    const int lane = tid & 31;
    const int warp = tid >> 5;
    const int gid  = lane >> 2, tig = lane & 3;
    const int mrow = (warp >> 2) * 32;   // 0..32
    const int ncol = (warp & 3) * 64;    // 0..192

    const int which = blockIdx.y;
    const int row0  = blockIdx.x * 64;

    const float* x  = which ? xl : xg;
    const __nv_bfloat16* wT = g_wT + (size_t)which * 4 * KDIM * KDIM;
    const float* b1 = which ? lb1 : gb1;
    const float* b2 = which ? lb2 : gb2;
    const float* b3 = which ? lb3 : gb3;
    const float* bs = which ? lbs : gbs;
    __nv_bfloat16* gout = which ? g_lenc_bf : g_genc_bf;

    // ---- convert input fp32 -> bf16 into X (64x256 = 4096 float4) ----
#pragma unroll
    for (int it = 0; it < 16; it++) {
        int c   = tid + it * 256;
        int row = c >> 6;
        int kq  = (c & 63) * 4;
        float4 v = *(const float4*)(x + (size_t)(row0 + row) * KDIM + kq);
        uint2 u;
        u.x = pack_bf2(v.x, v.y);
        u.y = pack_bf2(v.z, v.w);
        *(uint2*)(smem + FF_X + (uint32_t)(row * FF_LDX + kq) * 2) = u;
    }
    __syncthreads();

    const uint32_t aL = (uint32_t)((mrow + (lane & 7) + ((lane >> 3) & 1) * 8)
                                   * FF_LDX + (lane >> 4) * 8) * 2;
    const uint32_t bL = (uint32_t)((ncol + (lane & 7) + (lane >> 4) * 8)
                                   * FF_LDW + ((lane >> 3) & 1) * 8) * 2;

    // shortcut: TMP = X @ WsT + bs   (X unchanged)
    ff_gemm(smem, s_base, 0, wT + 3 * KDIM * KDIM, bs, gout, row0,
            tid, mrow, ncol, gid, tig, aL, bL);
    // h1 = relu(X @ W1T + b1) -> X
    ff_gemm(smem, s_base, 1, wT + 0 * KDIM * KDIM, b1, gout, row0,
            tid, mrow, ncol, gid, tig, aL, bL);
    // h2 = relu(X @ W2T + b2) -> X
    ff_gemm(smem, s_base, 1, wT + 1 * KDIM * KDIM, b2, gout, row0,
            tid, mrow, ncol, gid, tig, aL, bL);
    // out = relu(X @ W3T + b3) + TMP -> global bf16
    ff_gemm(smem, s_base, 2, wT + 2 * KDIM * KDIM, b3, gout, row0,
            tid, mrow, ncol, gid, tig, aL, bL);
}

// ============================================================================
// Score GEMM: mma.sync bf16, 128x128 CTA tile, 4 K-chunks of 64, 2-stage
// cp.async pipeline, ldmatrix, fused JSD epilogue + last-block final reduce.
// Epilogue algebra: c = softplus(r) - LOG2;  neg-term = c;  pos-term = r - c.
// ============================================================================
#define LDK     72
#define STG_A   (128 * LDK * 2)
#define STG_SZ  (2 * STG_A)
#define SM_SIZE (2 * STG_SZ)

__global__ void __launch_bounds__(256, 2)
score_kernel(const float* __restrict__ adj, float* __restrict__ out)
{
    extern __shared__ char smem[];
    const uint32_t s_base = smem_u32(smem);

    const int tid  = threadIdx.x;
    const int lane = tid & 31;
    const int warp = tid >> 5;
    const int gid  = lane >> 2;
    const int tig  = lane & 3;
    const int mrow = (warp >> 1) * 32;
    const int ncol = (warp & 1) * 64;

    const int i0 = blockIdx.y * BT;
    const int j0 = blockIdx.x * BT;

#pragma unroll
    for (int t = tid; t < 512; t += 256) {
        int row = t >> 2, seg = t & 3;
        prefetch_l2(adj + (size_t)(i0 + row) * NDRUGS + j0 + seg * 32);
    }

    const int lrow = tid >> 3;
    const int lkq  = (tid & 7) * 8;
    auto issue = [&](int kc, int st) {
        const uint32_t a_s = s_base + st * STG_SZ;
        const uint32_t b_s = a_s + STG_A;
#pragma unroll
        for (int it = 0; it < 4; it++) {
            int row = lrow + it * 32;
            uint32_t soff = (uint32_t)(row * LDK + lkq) * 2;
            const size_t goff = (size_t)row * KDIM + kc * 64 + lkq;
            cp_async16(a_s + soff, g_lenc_bf + (size_t)i0 * KDIM + goff);
            cp_async16(b_s + soff, g_genc_bf + (size_t)j0 * KDIM + goff);
        }
        cp_async_commit();
    };

    const int a_row  = mrow + (lane & 7) + ((lane >> 3) & 1) * 8;
    const int a_koff = (lane >> 4) * 8;
    const uint32_t a_lane = (uint32_t)(a_row * LDK + a_koff) * 2;
    const int b_row  = ncol + (lane & 7) + (lane >> 4) * 8;
    const int b_koff = ((lane >> 3) & 1) * 8;
    const uint32_t b_lane = (uint32_t)(b_row * LDK + b_koff) * 2;

    float acc[2][8][4];
#pragma unroll
    for (int mt = 0; mt < 2; mt++)
#pragma unroll
        for (int nt = 0; nt < 8; nt++)
#pragma unroll
            for (int q = 0; q < 4; q++) acc[mt][nt][q] = 0.f;

    issue(0, 0);

#pragma unroll 1
    for (int kc = 0; kc < 4; kc++) {
        const int st = kc & 1;
        if (kc < 3) issue(kc + 1, st ^ 1);
        if (kc < 3) cp_async_wait<1>(); else cp_async_wait<0>();
        __syncthreads();

        const uint32_t a_s = s_base + st * STG_SZ + a_lane;
        const uint32_t b_s = s_base + st * STG_SZ + STG_A + b_lane;

#pragma unroll
        for (int ks = 0; ks < 4; ks++) {
            const uint32_t k0b = (uint32_t)(ks * 16) * 2;
            uint32_t bfr[8][2];
#pragma unroll
            for (int ntp = 0; ntp < 4; ntp++) {
                uint32_t r0, r1, r2, r3;
                ldmatrix_x4(r0, r1, r2, r3,
                            b_s + (uint32_t)(ntp * 16 * LDK) * 2 + k0b);
                bfr[2 * ntp][0]     = r0; bfr[2 * ntp][1]     = r1;
                bfr[2 * ntp + 1][0] = r2; bfr[2 * ntp + 1][1] = r3;
            }
#pragma unroll
            for (int mt = 0; mt < 2; mt++) {
                uint32_t a0, a1, a2, a3;
                ldmatrix_x4(a0, a1, a2, a3,
                            a_s + (uint32_t)(mt * 16 * LDK) * 2 + k0b);
#pragma unroll
                for (int nt = 0; nt < 8; nt++)
                    mma_bf16(acc[mt][nt][0], acc[mt][nt][1],
                             acc[mt][nt][2], acc[mt][nt][3],
                             a0, a1, a2, a3, bfr[nt][0], bfr[nt][1]);
            }
        }
        __syncthreads();
    }

    // ---- epilogue: cAcc over all, rare pos-branch corrections ----
    float cAcc = 0.f, pAcc = 0.f, nCorr = 0.f;
#pragma unroll
    for (int mt = 0; mt < 2; mt++) {
        const int r0 = i0 + mrow + mt * 16 + gid;
#pragma unroll
        for (int nt = 0; nt < 8; nt++) {
            const int c0 = j0 + ncol + nt * 8 + tig * 2;
            float2 alo = __ldg((const float2*)(adj + (size_t)r0 * NDRUGS + c0));
            float2 ahi = __ldg((const float2*)(adj + (size_t)(r0 + 8) * NDRUGS + c0));
            float aa[4] = {alo.x, alo.y, ahi.x, ahi.y};
#pragma unroll
            for (int q = 0; q < 4; q++) {
                float r = acc[mt][nt][q];
                float u = fmaxf(r, 0.f);
                float t = __logf(1.f + __expf(-fabsf(r)));
                float c = u + t - LOG2F_;   // softplus(r) - LOG2
                cAcc += c;
                if (aa[q] != 0.0f) {        // ~1% dense
                    pAcc  += r - c;         // LOG2 - softplus(-r)
                    nCorr += c;
                }
            }
        }
    }
    float pos = pAcc;
    float neg = cAcc - nCorr;

    float* red = (float*)smem;
    __syncthreads();
    red[tid] = pos; red[256 + tid] = neg;
    __syncthreads();
#pragma unroll
    for (int s = 128; s > 0; s >>= 1) {
        if (tid < s) { red[tid] += red[tid + s]; red[256 + tid] += red[256 + tid + s]; }
        __syncthreads();
    }

    // ---- publish partial, detect last block ----
    __shared__ unsigned int isLast;
    if (tid == 0) {
        int bid = blockIdx.y * gridDim.x + blockIdx.x;
        g_partials[bid]        = red[0];
        g_partials[NBLK + bid] = red[256];
        __threadfence();
        unsigned int v = atomicAdd(&g_done, 1u);
        isLast = (v == (unsigned int)(NBLK - 1)) ? 1u : 0u;
    }
    __syncthreads();

    // ---- last block performs the deterministic final reduction ----
    if (isLast) {
        __threadfence();
        double* dsp = (double*)smem;
        double* dsn = dsp + 256;
        double p = 0.0, n = 0.0;
#pragma unroll 4
        for (int i = tid; i < NBLK; i += 256) {
            p += (double)g_partials[i];
            n += (double)g_partials[NBLK + i];
        }
        dsp[tid] = p; dsn[tid] = n;
        __syncthreads();
#pragma unroll
        for (int s = 128; s > 0; s >>= 1) {
            if (tid < s) { dsp[tid] += dsp[tid + s]; dsn[tid] += dsn[tid + s]; }
            __syncthreads();
        }
        if (tid == 0) {
            double E_pos = dsp[0] / (double)NDRUGS;
            double E_neg = dsn[0] / ((double)NDRUGS * (double)(NDRUGS - 1));
            out[0] = (float)(E_neg - E_pos);
            g_done = 0;   // reset for next graph replay
        }
    }
}

// ============================================================================
// launch
// ============================================================================
extern "C" void kernel_launch(void* const* d_in, const int* in_sizes, int n_in,
                              void* d_out, int out_size)
{
    const float* emb  = (const float*)d_in[0];
    const float* feat = (const float*)d_in[1];
    const float* adj  = (const float*)d_in[2];
    const float* g_w1 = (const float*)d_in[4];
    const float* g_b1 = (const float*)d_in[5];
    const float* g_w2 = (const float*)d_in[6];
    const float* g_b2 = (const float*)d_in[7];
    const float* g_w3 = (const float*)d_in[8];
    const float* g_b3 = (const float*)d_in[9];
    const float* g_ws = (const float*)d_in[10];
    const float* g_bs = (const float*)d_in[11];
    const float* l_w1 = (const float*)d_in[12];
    const float* l_b1 = (const float*)d_in[13];
    const float* l_w2 = (const float*)d_in[14];
    const float* l_b2 = (const float*)d_in[15];
    const float* l_w3 = (const float*)d_in[16];
    const float* l_b3 = (const float*)d_in[17];
    const float* l_ws = (const float*)d_in[18];
    const float* l_bs = (const float*)d_in[19];
    float* out = (float*)d_out;

    cudaFuncSetAttribute(score_kernel,
                         cudaFuncAttributeMaxDynamicSharedMemorySize, SM_SIZE);
    cudaFuncSetAttribute(ff_mma_kernel,
                         cudaFuncAttributeMaxDynamicSharedMemorySize, FF_SMEM);

    dim3 tgrid(64, 8);
    wT_kernel<<<tgrid, 256>>>(g_w1, g_w2, g_w3, g_ws, l_w1, l_w2, l_w3, l_ws);

    dim3 fgrid(NDRUGS / 64, 2);
    ff_mma_kernel<<<fgrid, 256, FF_SMEM>>>(emb, feat,
                                           g_b1, g_b2, g_b3, g_bs,
                                           l_b1, l_b2, l_b3, l_bs);

    dim3 grid(NDRUGS / BT, NDRUGS / BT);
    score_kernel<<<grid, 256, SM_SIZE>>>(adj, out);
}